// round 1
// baseline (speedup 1.0000x reference)
#include <cuda_runtime.h>

// Problem constants
#define B_    2
#define S_    2048
#define D_    1024
#define H_    16
#define DH_   64
#define MTOT  (B_ * S_)   // 4096 rows

// Scratch (no cudaMalloc allowed): Q, K, V, attention-output, each [4096,1024] f32.
__device__ float g_q[(size_t)MTOT * D_];
__device__ float g_k[(size_t)MTOT * D_];
__device__ float g_v[(size_t)MTOT * D_];
__device__ float g_o[(size_t)MTOT * D_];

// ---------------------------------------------------------------------------
// GEMM (NT): C[M,N] = A[M,K] * W[N,K]^T   (torch Linear: y = x @ W.T)
// M = 4096, N = 1024, K = 1024. 128x128 tile, TK=8, 256 threads, 8x8 microtile.
// ---------------------------------------------------------------------------
__global__ __launch_bounds__(256) void gemm_nt(const float* __restrict__ A,
                                               const float* __restrict__ W,
                                               float* __restrict__ C)
{
    constexpr int N = D_;
    constexpr int K = D_;

    __shared__ float As[8][128];
    __shared__ float Bs[8][128];

    const int tid = threadIdx.x;
    const int bm = blockIdx.y * 128;
    const int bn = blockIdx.x * 128;

    const int lr = tid >> 1;          // 0..127 : row within tile for loading
    const int lc = (tid & 1) * 4;     // 0 or 4 : k-offset for loading
    const int tm = (tid >> 4) * 8;    // 0..120 : microtile row
    const int tn = (tid & 15) * 8;    // 0..120 : microtile col

    float acc[8][8];
#pragma unroll
    for (int i = 0; i < 8; i++)
#pragma unroll
        for (int j = 0; j < 8; j++) acc[i][j] = 0.f;

    const float* Ap = A + (size_t)(bm + lr) * K + lc;
    const float* Wp = W + (size_t)(bn + lr) * K + lc;

    for (int k0 = 0; k0 < K; k0 += 8) {
        float4 a4 = *(const float4*)(Ap + k0);
        float4 b4 = *(const float4*)(Wp + k0);
        As[lc + 0][lr] = a4.x; As[lc + 1][lr] = a4.y;
        As[lc + 2][lr] = a4.z; As[lc + 3][lr] = a4.w;
        Bs[lc + 0][lr] = b4.x; Bs[lc + 1][lr] = b4.y;
        Bs[lc + 2][lr] = b4.z; Bs[lc + 3][lr] = b4.w;
        __syncthreads();

#pragma unroll
        for (int kk = 0; kk < 8; kk++) {
            float a[8], b[8];
#pragma unroll
            for (int i = 0; i < 8; i++) a[i] = As[kk][tm + i];
#pragma unroll
            for (int j = 0; j < 8; j++) b[j] = Bs[kk][tn + j];
#pragma unroll
            for (int i = 0; i < 8; i++)
#pragma unroll
                for (int j = 0; j < 8; j++)
                    acc[i][j] += a[i] * b[j];
        }
        __syncthreads();
    }

#pragma unroll
    for (int i = 0; i < 8; i++) {
        float* Cp = C + (size_t)(bm + tm + i) * N + bn + tn;
        float4 v0 = make_float4(acc[i][0], acc[i][1], acc[i][2], acc[i][3]);
        float4 v1 = make_float4(acc[i][4], acc[i][5], acc[i][6], acc[i][7]);
        *(float4*)(Cp + 0) = v0;
        *(float4*)(Cp + 4) = v1;
    }
}

// ---------------------------------------------------------------------------
// Causal flash attention, fp32. One block per (q-tile of 64, b*h).
// 64 threads; thread = one query row. q + acc in registers; K/V/score tiles
// in shared. K/V inner reads are warp-broadcast (all lanes read the same
// word) -> conflict-free, FMA-issue bound.
// ---------------------------------------------------------------------------
__global__ __launch_bounds__(64) void flash_attn(const float* __restrict__ Q,
                                                 const float* __restrict__ Kg,
                                                 const float* __restrict__ Vg,
                                                 float* __restrict__ O)
{
    __shared__ float Ks[64][64];
    __shared__ float Vs[64][64];
    __shared__ float Sc[64][64];   // Sc[j][tid]: per-lane column -> conflict-free

    const int qt  = blockIdx.x;        // 0..31 q tile
    const int bh  = blockIdx.y;        // 0..31 (b*16 + h)
    const int b   = bh >> 4;
    const int h   = bh & 15;
    const int tid = threadIdx.x;

    const size_t base = (size_t)b * S_ * D_ + (size_t)h * DH_;
    const float* Qb = Q  + base;
    const float* Kb = Kg + base;
    const float* Vb = Vg + base;

    const int qrow = qt * 64 + tid;

    float q[64];
    {
        const float4* qp = (const float4*)(Qb + (size_t)qrow * D_);
#pragma unroll
        for (int i = 0; i < 16; i++) {
            float4 t = qp[i];
            q[4*i+0] = t.x; q[4*i+1] = t.y; q[4*i+2] = t.z; q[4*i+3] = t.w;
        }
    }

    float acc[64];
#pragma unroll
    for (int d = 0; d < 64; d++) acc[d] = 0.f;
    float m = -1e30f;
    float l = 0.f;

    for (int kt = 0; kt <= qt; kt++) {
        // Cooperative coalesced load of K/V tiles [64 x 64]
#pragma unroll
        for (int i = 0; i < 16; i++) {
            int idx = i * 64 + tid;
            int r = idx >> 4;
            int c = idx & 15;
            ((float4*)Ks[r])[c] = *(const float4*)(Kb + (size_t)(kt*64 + r) * D_ + c*4);
            ((float4*)Vs[r])[c] = *(const float4*)(Vb + (size_t)(kt*64 + r) * D_ + c*4);
        }
        __syncthreads();

        const bool diag = (kt == qt);
        float mt = m;

        // Pass A: scores for this thread's query row
#pragma unroll 2
        for (int j = 0; j < 64; j++) {
            const float4* kr = (const float4*)Ks[j];
            float s0 = 0.f, s1 = 0.f, s2 = 0.f, s3 = 0.f;
#pragma unroll
            for (int i = 0; i < 16; i++) {
                float4 kv = kr[i];
                s0 += q[4*i+0] * kv.x;
                s1 += q[4*i+1] * kv.y;
                s2 += q[4*i+2] * kv.z;
                s3 += q[4*i+3] * kv.w;
            }
            float s = ((s0 + s1) + (s2 + s3)) * 0.125f;   // 1/sqrt(64)
            if (diag && (kt*64 + j) > qrow) s = -1e30f;
            Sc[j][tid] = s;
            mt = fmaxf(mt, s);
        }

        const float alpha = __expf(m - mt);
        m = mt;
        l *= alpha;
#pragma unroll
        for (int d = 0; d < 64; d++) acc[d] *= alpha;

        // Pass B: softmax weights + PV accumulation
#pragma unroll 2
        for (int j = 0; j < 64; j++) {
            float p = __expf(Sc[j][tid] - mt);
            l += p;
            const float4* vr = (const float4*)Vs[j];
#pragma unroll
            for (int i = 0; i < 16; i++) {
                float4 vv = vr[i];
                acc[4*i+0] += p * vv.x;
                acc[4*i+1] += p * vv.y;
                acc[4*i+2] += p * vv.z;
                acc[4*i+3] += p * vv.w;
            }
        }
        __syncthreads();
    }

    const float inv = 1.f / l;
    float* Op = O + base + (size_t)qrow * D_;
#pragma unroll
    for (int i = 0; i < 16; i++) {
        float4 t;
        t.x = acc[4*i+0] * inv;
        t.y = acc[4*i+1] * inv;
        t.z = acc[4*i+2] * inv;
        t.w = acc[4*i+3] * inv;
        *(float4*)(Op + 4*i) = t;
    }
}

// ---------------------------------------------------------------------------
extern "C" void kernel_launch(void* const* d_in, const int* in_sizes, int n_in,
                              void* d_out, int out_size)
{
    const float* x  = (const float*)d_in[0];
    const float* Wq = (const float*)d_in[1];
    const float* Wk = (const float*)d_in[2];
    const float* Wv = (const float*)d_in[3];
    const float* Wo = (const float*)d_in[4];
    float* out = (float*)d_out;

    float *q, *k, *v, *o;
    cudaGetSymbolAddress((void**)&q, g_q);
    cudaGetSymbolAddress((void**)&k, g_k);
    cudaGetSymbolAddress((void**)&v, g_v);
    cudaGetSymbolAddress((void**)&o, g_o);

    dim3 gg(D_ / 128, MTOT / 128);   // (8, 32)

    gemm_nt<<<gg, 256>>>(x, Wq, q);
    gemm_nt<<<gg, 256>>>(x, Wk, k);
    gemm_nt<<<gg, 256>>>(x, Wv, v);

    flash_attn<<<dim3(S_ / 64, B_ * H_), 64>>>(q, k, v, o);

    gemm_nt<<<gg, 256>>>(o, Wo, out);
}

// round 2
// speedup vs baseline: 1.4333x; 1.4333x over previous
#include <cuda_runtime.h>
#include <cstdint>

// Problem constants
#define B_    2
#define S_    2048
#define D_    1024
#define H_    16
#define DH_   64
#define MTOT  (B_ * S_)   // 4096 rows

// Scratch (no cudaMalloc allowed): Q, K, V, attention-output, each [4096,1024] f32.
__device__ float g_q[(size_t)MTOT * D_];
__device__ float g_k[(size_t)MTOT * D_];
__device__ float g_v[(size_t)MTOT * D_];
__device__ float g_o[(size_t)MTOT * D_];

// ---------------------------------------------------------------------------
// tf32 helpers
// ---------------------------------------------------------------------------
__device__ __forceinline__ uint32_t f2tf32(float x) {
    uint32_t t;
    asm("cvt.rna.tf32.f32 %0, %1;" : "=r"(t) : "f"(x));
    return t;
}

__device__ __forceinline__ void mma_tf32(float& c0, float& c1, float& c2, float& c3,
                                         uint32_t a0, uint32_t a1, uint32_t a2, uint32_t a3,
                                         uint32_t b0, uint32_t b1) {
    asm volatile(
        "mma.sync.aligned.m16n8k8.row.col.f32.tf32.tf32.f32 "
        "{%0,%1,%2,%3}, {%4,%5,%6,%7}, {%8,%9}, {%0,%1,%2,%3};"
        : "+f"(c0), "+f"(c1), "+f"(c2), "+f"(c3)
        : "r"(a0), "r"(a1), "r"(a2), "r"(a3), "r"(b0), "r"(b1));
}

// ---------------------------------------------------------------------------
// tf32 tensor-core GEMM (NT): C[M,N] = A[M,K] * W[N,K]^T
// Block tile 128x128, BK=16, 256 threads = 8 warps (2 m x 4 n), warp tile
// 64x32 = 4x4 m16n8k8 mma tiles. Smem k-major, row stride 136 floats ->
// fragment gathers are bank-conflict-free (bank = (8*tg + g + m) mod 32,
// a bijection over the warp).
// ---------------------------------------------------------------------------
#define GBK   16
#define GLDS  136

__global__ __launch_bounds__(256) void gemm_nt_tf32(const float* __restrict__ A,
                                                    const float* __restrict__ W,
                                                    float* __restrict__ C)
{
    constexpr int N = D_;
    constexpr int K = D_;

    __shared__ uint32_t As[GBK][GLDS];
    __shared__ uint32_t Bs[GBK][GLDS];

    const int tid  = threadIdx.x;
    const int bm   = blockIdx.y * 128;
    const int bn   = blockIdx.x * 128;
    const int lane = tid & 31;
    const int warp = tid >> 5;
    const int g    = lane >> 2;   // group id 0..7
    const int tg   = lane & 3;    // thread-in-group 0..3
    const int wm   = (warp >> 2) * 64;  // warp m offset 0/64
    const int wn   = (warp & 3) * 32;   // warp n offset 0..96

    // Global load mapping: 2 float4 per thread per tile (A and W each).
    const int r0 = (tid) >> 1;                 // not used; see idx scheme below
    (void)r0;

    float4 ga[2], gb[2];
    int arow[2], acol[2];
#pragma unroll
    for (int it = 0; it < 2; it++) {
        int idx = it * 256 + tid;
        arow[it] = idx >> 2;          // 0..127
        acol[it] = (idx & 3) * 4;     // 0,4,8,12
    }

    const float* Abase = A + (size_t)bm * K;
    const float* Wbase = W + (size_t)bn * K;

    // preload tile 0
#pragma unroll
    for (int it = 0; it < 2; it++) {
        ga[it] = *(const float4*)(Abase + (size_t)arow[it] * K + acol[it]);
        gb[it] = *(const float4*)(Wbase + (size_t)arow[it] * K + acol[it]);
    }

    float c[4][4][4];   // [mi][ni][frag]
#pragma unroll
    for (int mi = 0; mi < 4; mi++)
#pragma unroll
        for (int ni = 0; ni < 4; ni++)
#pragma unroll
            for (int f = 0; f < 4; f++) c[mi][ni][f] = 0.f;

    const int NT = K / GBK;   // 64
    for (int t = 0; t < NT; t++) {
        if (t > 0) __syncthreads();
        // store regs -> smem (converted to tf32), k-major
#pragma unroll
        for (int it = 0; it < 2; it++) {
            int r = arow[it], cc = acol[it];
            As[cc + 0][r] = f2tf32(ga[it].x);
            As[cc + 1][r] = f2tf32(ga[it].y);
            As[cc + 2][r] = f2tf32(ga[it].z);
            As[cc + 3][r] = f2tf32(ga[it].w);
            Bs[cc + 0][r] = f2tf32(gb[it].x);
            Bs[cc + 1][r] = f2tf32(gb[it].y);
            Bs[cc + 2][r] = f2tf32(gb[it].z);
            Bs[cc + 3][r] = f2tf32(gb[it].w);
        }
        __syncthreads();

        // prefetch next tile
        if (t + 1 < NT) {
            int k0 = (t + 1) * GBK;
#pragma unroll
            for (int it = 0; it < 2; it++) {
                ga[it] = *(const float4*)(Abase + (size_t)arow[it] * K + k0 + acol[it]);
                gb[it] = *(const float4*)(Wbase + (size_t)arow[it] * K + k0 + acol[it]);
            }
        }

        // compute: 2 k8 steps
#pragma unroll
        for (int kk = 0; kk < GBK; kk += 8) {
            uint32_t af[4][4], bf[4][2];
#pragma unroll
            for (int mi = 0; mi < 4; mi++) {
                int m = wm + mi * 16 + g;
                af[mi][0] = As[kk + tg][m];
                af[mi][1] = As[kk + tg][m + 8];
                af[mi][2] = As[kk + tg + 4][m];
                af[mi][3] = As[kk + tg + 4][m + 8];
            }
#pragma unroll
            for (int ni = 0; ni < 4; ni++) {
                int n = wn + ni * 8 + g;
                bf[ni][0] = Bs[kk + tg][n];
                bf[ni][1] = Bs[kk + tg + 4][n];
            }
#pragma unroll
            for (int mi = 0; mi < 4; mi++)
#pragma unroll
                for (int ni = 0; ni < 4; ni++)
                    mma_tf32(c[mi][ni][0], c[mi][ni][1], c[mi][ni][2], c[mi][ni][3],
                             af[mi][0], af[mi][1], af[mi][2], af[mi][3],
                             bf[ni][0], bf[ni][1]);
        }
    }

    // epilogue
#pragma unroll
    for (int mi = 0; mi < 4; mi++) {
#pragma unroll
        for (int ni = 0; ni < 4; ni++) {
            int row = bm + wm + mi * 16 + g;
            int col = bn + wn + ni * 8 + 2 * tg;
            float2 v0 = make_float2(c[mi][ni][0], c[mi][ni][1]);
            float2 v1 = make_float2(c[mi][ni][2], c[mi][ni][3]);
            *(float2*)(C + (size_t)row * N + col)       = v0;
            *(float2*)(C + (size_t)(row + 8) * N + col) = v1;
        }
    }
}

// ---------------------------------------------------------------------------
// Causal flash attention, fp32 (unchanged from R0).
// ---------------------------------------------------------------------------
__global__ __launch_bounds__(64) void flash_attn(const float* __restrict__ Q,
                                                 const float* __restrict__ Kg,
                                                 const float* __restrict__ Vg,
                                                 float* __restrict__ O)
{
    __shared__ float Ks[64][64];
    __shared__ float Vs[64][64];
    __shared__ float Sc[64][64];

    const int qt  = blockIdx.x;
    const int bh  = blockIdx.y;
    const int b   = bh >> 4;
    const int h   = bh & 15;
    const int tid = threadIdx.x;

    const size_t base = (size_t)b * S_ * D_ + (size_t)h * DH_;
    const float* Qb = Q  + base;
    const float* Kb = Kg + base;
    const float* Vb = Vg + base;

    const int qrow = qt * 64 + tid;

    float q[64];
    {
        const float4* qp = (const float4*)(Qb + (size_t)qrow * D_);
#pragma unroll
        for (int i = 0; i < 16; i++) {
            float4 t = qp[i];
            q[4*i+0] = t.x; q[4*i+1] = t.y; q[4*i+2] = t.z; q[4*i+3] = t.w;
        }
    }

    float acc[64];
#pragma unroll
    for (int d = 0; d < 64; d++) acc[d] = 0.f;
    float m = -1e30f;
    float l = 0.f;

    for (int kt = 0; kt <= qt; kt++) {
#pragma unroll
        for (int i = 0; i < 16; i++) {
            int idx = i * 64 + tid;
            int r = idx >> 4;
            int c = idx & 15;
            ((float4*)Ks[r])[c] = *(const float4*)(Kb + (size_t)(kt*64 + r) * D_ + c*4);
            ((float4*)Vs[r])[c] = *(const float4*)(Vb + (size_t)(kt*64 + r) * D_ + c*4);
        }
        __syncthreads();

        const bool diag = (kt == qt);
        float mt = m;

#pragma unroll 2
        for (int j = 0; j < 64; j++) {
            const float4* kr = (const float4*)Ks[j];
            float s0 = 0.f, s1 = 0.f, s2 = 0.f, s3 = 0.f;
#pragma unroll
            for (int i = 0; i < 16; i++) {
                float4 kv = kr[i];
                s0 += q[4*i+0] * kv.x;
                s1 += q[4*i+1] * kv.y;
                s2 += q[4*i+2] * kv.z;
                s3 += q[4*i+3] * kv.w;
            }
            float s = ((s0 + s1) + (s2 + s3)) * 0.125f;
            if (diag && (kt*64 + j) > qrow) s = -1e30f;
            Sc[j][tid] = s;
            mt = fmaxf(mt, s);
        }

        const float alpha = __expf(m - mt);
        m = mt;
        l *= alpha;
#pragma unroll
        for (int d = 0; d < 64; d++) acc[d] *= alpha;

#pragma unroll 2
        for (int j = 0; j < 64; j++) {
            float p = __expf(Sc[j][tid] - mt);
            l += p;
            const float4* vr = (const float4*)Vs[j];
#pragma unroll
            for (int i = 0; i < 16; i++) {
                float4 vv = vr[i];
                acc[4*i+0] += p * vv.x;
                acc[4*i+1] += p * vv.y;
                acc[4*i+2] += p * vv.z;
                acc[4*i+3] += p * vv.w;
            }
        }
        __syncthreads();
    }

    const float inv = 1.f / l;
    float* Op = O + base + (size_t)qrow * D_;
#pragma unroll
    for (int i = 0; i < 16; i++) {
        float4 t;
        t.x = acc[4*i+0] * inv;
        t.y = acc[4*i+1] * inv;
        t.z = acc[4*i+2] * inv;
        t.w = acc[4*i+3] * inv;
        *(float4*)(Op + 4*i) = t;
    }
}

// ---------------------------------------------------------------------------
extern "C" void kernel_launch(void* const* d_in, const int* in_sizes, int n_in,
                              void* d_out, int out_size)
{
    const float* x  = (const float*)d_in[0];
    const float* Wq = (const float*)d_in[1];
    const float* Wk = (const float*)d_in[2];
    const float* Wv = (const float*)d_in[3];
    const float* Wo = (const float*)d_in[4];
    float* out = (float*)d_out;

    float *q, *k, *v, *o;
    cudaGetSymbolAddress((void**)&q, g_q);
    cudaGetSymbolAddress((void**)&k, g_k);
    cudaGetSymbolAddress((void**)&v, g_v);
    cudaGetSymbolAddress((void**)&o, g_o);

    dim3 gg(D_ / 128, MTOT / 128);   // (8, 32)

    gemm_nt_tf32<<<gg, 256>>>(x, Wq, q);
    gemm_nt_tf32<<<gg, 256>>>(x, Wk, k);
    gemm_nt_tf32<<<gg, 256>>>(x, Wv, v);

    flash_attn<<<dim3(S_ / 64, B_ * H_), 64>>>(q, k, v, o);

    gemm_nt_tf32<<<gg, 256>>>(o, Wo, out);
}

// round 4
// speedup vs baseline: 2.7516x; 1.9198x over previous
#include <cuda_runtime.h>
#include <cstdint>

// Problem constants
#define B_    2
#define S_    2048
#define D_    1024
#define H_    16
#define DH_   64
#define MTOT  (B_ * S_)   // 4096 rows

__device__ float g_q[(size_t)MTOT * D_];
__device__ float g_k[(size_t)MTOT * D_];
__device__ float g_v[(size_t)MTOT * D_];
__device__ float g_o[(size_t)MTOT * D_];

// ---------------------------------------------------------------------------
// tf32 helpers
// ---------------------------------------------------------------------------
__device__ __forceinline__ uint32_t f2tf32(float x) {
    uint32_t t;
    asm("cvt.rna.tf32.f32 %0, %1;" : "=r"(t) : "f"(x));
    return t;
}

__device__ __forceinline__ void mma_tf32(float& c0, float& c1, float& c2, float& c3,
                                         uint32_t a0, uint32_t a1, uint32_t a2, uint32_t a3,
                                         uint32_t b0, uint32_t b1) {
    asm volatile(
        "mma.sync.aligned.m16n8k8.row.col.f32.tf32.tf32.f32 "
        "{%0,%1,%2,%3}, {%4,%5,%6,%7}, {%8,%9}, {%0,%1,%2,%3};"
        : "+f"(c0), "+f"(c1), "+f"(c2), "+f"(c3)
        : "r"(a0), "r"(a1), "r"(a2), "r"(a3), "r"(b0), "r"(b1));
}

// ---------------------------------------------------------------------------
// tf32 tensor-core GEMM (NT): C = A[M,K] * W[N,K]^T   (unchanged from R1)
// ---------------------------------------------------------------------------
#define GBK   16
#define GLDS  136

__global__ __launch_bounds__(256) void gemm_nt_tf32(const float* __restrict__ A,
                                                    const float* __restrict__ W,
                                                    float* __restrict__ C)
{
    constexpr int N = D_;
    constexpr int K = D_;

    __shared__ uint32_t As[GBK][GLDS];
    __shared__ uint32_t Bs[GBK][GLDS];

    const int tid  = threadIdx.x;
    const int bm   = blockIdx.y * 128;
    const int bn   = blockIdx.x * 128;
    const int lane = tid & 31;
    const int warp = tid >> 5;
    const int g    = lane >> 2;
    const int tg   = lane & 3;
    const int wm   = (warp >> 2) * 64;
    const int wn   = (warp & 3) * 32;

    float4 ga[2], gb[2];
    int arow[2], acol[2];
#pragma unroll
    for (int it = 0; it < 2; it++) {
        int idx = it * 256 + tid;
        arow[it] = idx >> 2;
        acol[it] = (idx & 3) * 4;
    }

    const float* Abase = A + (size_t)bm * K;
    const float* Wbase = W + (size_t)bn * K;

#pragma unroll
    for (int it = 0; it < 2; it++) {
        ga[it] = *(const float4*)(Abase + (size_t)arow[it] * K + acol[it]);
        gb[it] = *(const float4*)(Wbase + (size_t)arow[it] * K + acol[it]);
    }

    float c[4][4][4];
#pragma unroll
    for (int mi = 0; mi < 4; mi++)
#pragma unroll
        for (int ni = 0; ni < 4; ni++)
#pragma unroll
            for (int f = 0; f < 4; f++) c[mi][ni][f] = 0.f;

    const int NT = K / GBK;
    for (int t = 0; t < NT; t++) {
        if (t > 0) __syncthreads();
#pragma unroll
        for (int it = 0; it < 2; it++) {
            int r = arow[it], cc = acol[it];
            As[cc + 0][r] = f2tf32(ga[it].x);
            As[cc + 1][r] = f2tf32(ga[it].y);
            As[cc + 2][r] = f2tf32(ga[it].z);
            As[cc + 3][r] = f2tf32(ga[it].w);
            Bs[cc + 0][r] = f2tf32(gb[it].x);
            Bs[cc + 1][r] = f2tf32(gb[it].y);
            Bs[cc + 2][r] = f2tf32(gb[it].z);
            Bs[cc + 3][r] = f2tf32(gb[it].w);
        }
        __syncthreads();

        if (t + 1 < NT) {
            int k0 = (t + 1) * GBK;
#pragma unroll
            for (int it = 0; it < 2; it++) {
                ga[it] = *(const float4*)(Abase + (size_t)arow[it] * K + k0 + acol[it]);
                gb[it] = *(const float4*)(Wbase + (size_t)arow[it] * K + k0 + acol[it]);
            }
        }

#pragma unroll
        for (int kk = 0; kk < GBK; kk += 8) {
            uint32_t af[4][4], bf[4][2];
#pragma unroll
            for (int mi = 0; mi < 4; mi++) {
                int m = wm + mi * 16 + g;
                af[mi][0] = As[kk + tg][m];
                af[mi][1] = As[kk + tg][m + 8];
                af[mi][2] = As[kk + tg + 4][m];
                af[mi][3] = As[kk + tg + 4][m + 8];
            }
#pragma unroll
            for (int ni = 0; ni < 4; ni++) {
                int n = wn + ni * 8 + g;
                bf[ni][0] = Bs[kk + tg][n];
                bf[ni][1] = Bs[kk + tg + 4][n];
            }
#pragma unroll
            for (int mi = 0; mi < 4; mi++)
#pragma unroll
                for (int ni = 0; ni < 4; ni++)
                    mma_tf32(c[mi][ni][0], c[mi][ni][1], c[mi][ni][2], c[mi][ni][3],
                             af[mi][0], af[mi][1], af[mi][2], af[mi][3],
                             bf[ni][0], bf[ni][1]);
        }
    }

#pragma unroll
    for (int mi = 0; mi < 4; mi++) {
#pragma unroll
        for (int ni = 0; ni < 4; ni++) {
            int row = bm + wm + mi * 16 + g;
            int col = bn + wn + ni * 8 + 2 * tg;
            *(float2*)(C + (size_t)row * N + col)       = make_float2(c[mi][ni][0], c[mi][ni][1]);
            *(float2*)(C + (size_t)(row + 8) * N + col) = make_float2(c[mi][ni][2], c[mi][ni][3]);
        }
    }
}

// ---------------------------------------------------------------------------
// Tensor-core causal flash attention (tf32 mma.sync).
// Block = 128 q-rows x one (b,h). 8 warps, warp owns 16 rows.
// Q fragments in registers; K tile transposed in smem (stride 76),
// V tile direct (stride 72), P staged in smem k-major (stride 136,
// per-warp-private columns -> __syncwarp only).
// ---------------------------------------------------------------------------
#define PQ_STR 136
#define K_STR  76
#define V_STR  72
#define FA_SMEM_U32 (64*PQ_STR + 64*K_STR + 64*V_STR)
#define FA_SMEM_B   (FA_SMEM_U32 * 4)

__global__ __launch_bounds__(256) void flash_attn_tc(const float* __restrict__ Qg,
                                                     const float* __restrict__ Kg,
                                                     const float* __restrict__ Vg,
                                                     float* __restrict__ Og)
{
    extern __shared__ uint32_t sm[];
    uint32_t* Qs = sm;                      // [64][136]  (reused as Ps)
    uint32_t* Ks = sm + 64 * PQ_STR;        // [64][76]   (d-major, transposed)
    uint32_t* Vs = Ks + 64 * K_STR;         // [64][72]   (k-major, direct)

    const int qt   = blockIdx.x;
    const int bh   = blockIdx.y;
    const int b    = bh >> 4;
    const int h    = bh & 15;
    const int tid  = threadIdx.x;
    const int lane = tid & 31;
    const int warp = tid >> 5;
    const int g    = lane >> 2;
    const int tg   = lane & 3;
    const int m0   = warp * 16;
    const int q0   = qt * 128;

    const size_t base = (size_t)b * S_ * D_ + (size_t)h * DH_;

    // ---- load Q tile [128x64] -> Qs[d][m], scaled by 1/8, tf32 ----
#pragma unroll
    for (int it = 0; it < 8; it++) {
        int idx = it * 256 + tid;
        int r = (idx >> 2) & 127;
        int c = 4 * (idx & 3) + 16 * (idx >> 9);
        float4 t = *(const float4*)(Qg + base + (size_t)(q0 + r) * D_ + c);
        Qs[(c + 0) * PQ_STR + r] = f2tf32(t.x * 0.125f);
        Qs[(c + 1) * PQ_STR + r] = f2tf32(t.y * 0.125f);
        Qs[(c + 2) * PQ_STR + r] = f2tf32(t.z * 0.125f);
        Qs[(c + 3) * PQ_STR + r] = f2tf32(t.w * 0.125f);
    }
    __syncthreads();

    uint32_t qf[8][4];
#pragma unroll
    for (int kk2 = 0; kk2 < 8; kk2++) {
        qf[kk2][0] = Qs[(8 * kk2 + tg) * PQ_STR + m0 + g];
        qf[kk2][1] = Qs[(8 * kk2 + tg) * PQ_STR + m0 + g + 8];
        qf[kk2][2] = Qs[(8 * kk2 + tg + 4) * PQ_STR + m0 + g];
        qf[kk2][3] = Qs[(8 * kk2 + tg + 4) * PQ_STR + m0 + g + 8];
    }
    __syncthreads();   // Qs may now be reused as Ps

    float o[8][4];
#pragma unroll
    for (int ni = 0; ni < 8; ni++)
#pragma unroll
        for (int f = 0; f < 4; f++) o[ni][f] = 0.f;
    float mrow[2] = {-1e30f, -1e30f};
    float lrow[2] = {0.f, 0.f};

    const int nkt = 2 * qt + 2;
    for (int kt = 0; kt < nkt; kt++) {
        const int k0 = kt * 64;

        // ---- load K (transposed) and V (direct) tiles ----
#pragma unroll
        for (int it = 0; it < 4; it++) {
            int idx = it * 256 + tid;
            int r = (idx >> 2) & 63;
            int c = 4 * (idx & 3) + 16 * (idx >> 8);
            float4 tk = *(const float4*)(Kg + base + (size_t)(k0 + r) * D_ + c);
            float4 tv = *(const float4*)(Vg + base + (size_t)(k0 + r) * D_ + c);
            Ks[(c + 0) * K_STR + r] = f2tf32(tk.x);
            Ks[(c + 1) * K_STR + r] = f2tf32(tk.y);
            Ks[(c + 2) * K_STR + r] = f2tf32(tk.z);
            Ks[(c + 3) * K_STR + r] = f2tf32(tk.w);
            Vs[r * V_STR + c + 0] = f2tf32(tv.x);
            Vs[r * V_STR + c + 1] = f2tf32(tv.y);
            Vs[r * V_STR + c + 2] = f2tf32(tv.z);
            Vs[r * V_STR + c + 3] = f2tf32(tv.w);
        }
        __syncthreads();

        // ---- S = (Q/8) K^T ----
        float s[8][4];
#pragma unroll
        for (int ni = 0; ni < 8; ni++) {
            s[ni][0] = s[ni][1] = s[ni][2] = s[ni][3] = 0.f;
            int n = ni * 8 + g;
#pragma unroll
            for (int kk2 = 0; kk2 < 8; kk2++) {
                uint32_t b0 = Ks[(8 * kk2 + tg) * K_STR + n];
                uint32_t b1 = Ks[(8 * kk2 + tg + 4) * K_STR + n];
                mma_tf32(s[ni][0], s[ni][1], s[ni][2], s[ni][3],
                         qf[kk2][0], qf[kk2][1], qf[kk2][2], qf[kk2][3], b0, b1);
            }
        }

        // ---- causal mask (only the two diagonal tiles need it) ----
        if (kt >= 2 * qt) {
            int row0 = q0 + m0 + g;
            int row1 = row0 + 8;
#pragma unroll
            for (int ni = 0; ni < 8; ni++) {
                int c0 = k0 + ni * 8 + 2 * tg;
                if (c0     > row0) s[ni][0] = -1e30f;
                if (c0 + 1 > row0) s[ni][1] = -1e30f;
                if (c0     > row1) s[ni][2] = -1e30f;
                if (c0 + 1 > row1) s[ni][3] = -1e30f;
            }
        }

        // ---- online softmax (rows g, g+8 spread over the tg quad) ----
#pragma unroll
        for (int r2 = 0; r2 < 2; r2++) {
            float mx = -1e30f;
#pragma unroll
            for (int ni = 0; ni < 8; ni++)
                mx = fmaxf(mx, fmaxf(s[ni][2 * r2], s[ni][2 * r2 + 1]));
            mx = fmaxf(mx, __shfl_xor_sync(0xffffffffu, mx, 1));
            mx = fmaxf(mx, __shfl_xor_sync(0xffffffffu, mx, 2));
            float mnew  = fmaxf(mrow[r2], mx);
            float alpha = __expf(mrow[r2] - mnew);
            mrow[r2] = mnew;
            float rs = 0.f;
#pragma unroll
            for (int ni = 0; ni < 8; ni++) {
                float p0 = __expf(s[ni][2 * r2]     - mnew);
                float p1 = __expf(s[ni][2 * r2 + 1] - mnew);
                s[ni][2 * r2] = p0; s[ni][2 * r2 + 1] = p1;
                rs += p0 + p1;
            }
            rs += __shfl_xor_sync(0xffffffffu, rs, 1);
            rs += __shfl_xor_sync(0xffffffffu, rs, 2);
            lrow[r2] = lrow[r2] * alpha + rs;
#pragma unroll
            for (int ni = 0; ni < 8; ni++) {
                o[ni][2 * r2]     *= alpha;
                o[ni][2 * r2 + 1] *= alpha;
            }
        }

        // ---- stage P in smem (k-major); per-warp-private m columns ----
        uint32_t* Ps = Qs;
#pragma unroll
        for (int ni = 0; ni < 8; ni++) {
            int c0 = ni * 8 + 2 * tg;
            Ps[(c0)     * PQ_STR + m0 + g]     = f2tf32(s[ni][0]);
            Ps[(c0 + 1) * PQ_STR + m0 + g]     = f2tf32(s[ni][1]);
            Ps[(c0)     * PQ_STR + m0 + g + 8] = f2tf32(s[ni][2]);
            Ps[(c0 + 1) * PQ_STR + m0 + g + 8] = f2tf32(s[ni][3]);
        }
        __syncwarp();

        // ---- O += P V ----
#pragma unroll
        for (int kk2 = 0; kk2 < 8; kk2++) {
            uint32_t a0 = Ps[(8 * kk2 + tg) * PQ_STR + m0 + g];
            uint32_t a1 = Ps[(8 * kk2 + tg) * PQ_STR + m0 + g + 8];
            uint32_t a2 = Ps[(8 * kk2 + tg + 4) * PQ_STR + m0 + g];
            uint32_t a3 = Ps[(8 * kk2 + tg + 4) * PQ_STR + m0 + g + 8];
#pragma unroll
            for (int ni = 0; ni < 8; ni++) {
                uint32_t b0 = Vs[(8 * kk2 + tg) * V_STR + ni * 8 + g];
                uint32_t b1 = Vs[(8 * kk2 + tg + 4) * V_STR + ni * 8 + g];
                mma_tf32(o[ni][0], o[ni][1], o[ni][2], o[ni][3], a0, a1, a2, a3, b0, b1);
            }
        }
        __syncthreads();   // Ks/Vs reused next iteration
    }

    // ---- epilogue ----
    const float inv0 = 1.f / lrow[0];
    const float inv1 = 1.f / lrow[1];
    const int row0 = q0 + m0 + g;
#pragma unroll
    for (int ni = 0; ni < 8; ni++) {
        int col = ni * 8 + 2 * tg;
        *(float2*)(Og + base + (size_t)row0 * D_ + col) =
            make_float2(o[ni][0] * inv0, o[ni][1] * inv0);
        *(float2*)(Og + base + (size_t)(row0 + 8) * D_ + col) =
            make_float2(o[ni][2] * inv1, o[ni][3] * inv1);
    }
}

// ---------------------------------------------------------------------------
extern "C" void kernel_launch(void* const* d_in, const int* in_sizes, int n_in,
                              void* d_out, int out_size)
{
    const float* x  = (const float*)d_in[0];
    const float* Wq = (const float*)d_in[1];
    const float* Wk = (const float*)d_in[2];
    const float* Wv = (const float*)d_in[3];
    const float* Wo = (const float*)d_in[4];
    float* out = (float*)d_out;

    float *q, *k, *v, *o;
    cudaGetSymbolAddress((void**)&q, g_q);
    cudaGetSymbolAddress((void**)&k, g_k);
    cudaGetSymbolAddress((void**)&v, g_v);
    cudaGetSymbolAddress((void**)&o, g_o);

    static bool attr_set = false;
    if (!attr_set) {
        cudaFuncSetAttribute(flash_attn_tc,
                             cudaFuncAttributeMaxDynamicSharedMemorySize, FA_SMEM_B);
        attr_set = true;
    }

    dim3 gg(D_ / 128, MTOT / 128);   // (8, 32)

    gemm_nt_tf32<<<gg, 256>>>(x, Wq, q);
    gemm_nt_tf32<<<gg, 256>>>(x, Wk, k);
    gemm_nt_tf32<<<gg, 256>>>(x, Wv, v);

    flash_attn_tc<<<dim3(S_ / 128, B_ * H_), 256, FA_SMEM_B>>>(q, k, v, o);

    gemm_nt_tf32<<<gg, 256>>>(o, Wo, out);
}

// round 5
// speedup vs baseline: 2.8042x; 1.0191x over previous
#include <cuda_runtime.h>
#include <cstdint>

#define B_    2
#define S_    2048
#define D_    1024
#define H_    16
#define DH_   64
#define MTOT  (B_ * S_)

__device__ float g_q[(size_t)MTOT * D_];
__device__ float g_k[(size_t)MTOT * D_];
__device__ float g_v[(size_t)MTOT * D_];
__device__ float g_o[(size_t)MTOT * D_];

// ---------------------------------------------------------------------------
__device__ __forceinline__ uint32_t f2tf32(float x) {
    uint32_t t;
    asm("cvt.rna.tf32.f32 %0, %1;" : "=r"(t) : "f"(x));
    return t;
}

__device__ __forceinline__ void mma_tf32(float& c0, float& c1, float& c2, float& c3,
                                         uint32_t a0, uint32_t a1, uint32_t a2, uint32_t a3,
                                         uint32_t b0, uint32_t b1) {
    asm volatile(
        "mma.sync.aligned.m16n8k8.row.col.f32.tf32.tf32.f32 "
        "{%0,%1,%2,%3}, {%4,%5,%6,%7}, {%8,%9}, {%0,%1,%2,%3};"
        : "+f"(c0), "+f"(c1), "+f"(c2), "+f"(c3)
        : "r"(a0), "r"(a1), "r"(a2), "r"(a3), "r"(b0), "r"(b1));
}

__device__ __forceinline__ void cp_async16(uint32_t saddr, const void* g) {
    asm volatile("cp.async.cg.shared.global [%0], [%1], 16;" :: "r"(saddr), "l"(g));
}
__device__ __forceinline__ uint32_t smem_u32addr(const void* p) {
    uint32_t a;
    asm("{ .reg .u64 t; cvta.to.shared.u64 t, %1; cvt.u32.u64 %0, t; }" : "=r"(a) : "l"(p));
    return a;
}

// ---------------------------------------------------------------------------
// tf32 tensor-core GEMM (NT): C = A[M,K] * W[N,K]^T
// round_out: epilogue stores tf32-rounded values (for Q/K/V feeding flash).
// ---------------------------------------------------------------------------
#define GBK   16
#define GLDS  136

__global__ __launch_bounds__(256) void gemm_nt_tf32(const float* __restrict__ A,
                                                    const float* __restrict__ W0,
                                                    const float* __restrict__ W1,
                                                    const float* __restrict__ W2,
                                                    float* __restrict__ C0,
                                                    float* __restrict__ C1,
                                                    float* __restrict__ C2,
                                                    int round_out)
{
    constexpr int N = D_;
    constexpr int K = D_;

    const float* W = (blockIdx.z == 0) ? W0 : (blockIdx.z == 1) ? W1 : W2;
    float*       C = (blockIdx.z == 0) ? C0 : (blockIdx.z == 1) ? C1 : C2;

    __shared__ uint32_t As[GBK][GLDS];
    __shared__ uint32_t Bs[GBK][GLDS];

    const int tid  = threadIdx.x;
    const int bm   = blockIdx.y * 128;
    const int bn   = blockIdx.x * 128;
    const int lane = tid & 31;
    const int warp = tid >> 5;
    const int g    = lane >> 2;
    const int tg   = lane & 3;
    const int wm   = (warp >> 2) * 64;
    const int wn   = (warp & 3) * 32;

    float4 ga[2], gb[2];
    int arow[2], acol[2];
#pragma unroll
    for (int it = 0; it < 2; it++) {
        int idx = it * 256 + tid;
        arow[it] = idx >> 2;
        acol[it] = (idx & 3) * 4;
    }

    const float* Abase = A + (size_t)bm * K;
    const float* Wbase = W + (size_t)bn * K;

#pragma unroll
    for (int it = 0; it < 2; it++) {
        ga[it] = *(const float4*)(Abase + (size_t)arow[it] * K + acol[it]);
        gb[it] = *(const float4*)(Wbase + (size_t)arow[it] * K + acol[it]);
    }

    float c[4][4][4];
#pragma unroll
    for (int mi = 0; mi < 4; mi++)
#pragma unroll
        for (int ni = 0; ni < 4; ni++)
#pragma unroll
            for (int f = 0; f < 4; f++) c[mi][ni][f] = 0.f;

    const int NT = K / GBK;
    for (int t = 0; t < NT; t++) {
        if (t > 0) __syncthreads();
#pragma unroll
        for (int it = 0; it < 2; it++) {
            int r = arow[it], cc = acol[it];
            As[cc + 0][r] = f2tf32(ga[it].x);
            As[cc + 1][r] = f2tf32(ga[it].y);
            As[cc + 2][r] = f2tf32(ga[it].z);
            As[cc + 3][r] = f2tf32(ga[it].w);
            Bs[cc + 0][r] = f2tf32(gb[it].x);
            Bs[cc + 1][r] = f2tf32(gb[it].y);
            Bs[cc + 2][r] = f2tf32(gb[it].z);
            Bs[cc + 3][r] = f2tf32(gb[it].w);
        }
        __syncthreads();

        if (t + 1 < NT) {
            int k0 = (t + 1) * GBK;
#pragma unroll
            for (int it = 0; it < 2; it++) {
                ga[it] = *(const float4*)(Abase + (size_t)arow[it] * K + k0 + acol[it]);
                gb[it] = *(const float4*)(Wbase + (size_t)arow[it] * K + k0 + acol[it]);
            }
        }

#pragma unroll
        for (int kk = 0; kk < GBK; kk += 8) {
            uint32_t af[4][4], bf[4][2];
#pragma unroll
            for (int mi = 0; mi < 4; mi++) {
                int m = wm + mi * 16 + g;
                af[mi][0] = As[kk + tg][m];
                af[mi][1] = As[kk + tg][m + 8];
                af[mi][2] = As[kk + tg + 4][m];
                af[mi][3] = As[kk + tg + 4][m + 8];
            }
#pragma unroll
            for (int ni = 0; ni < 4; ni++) {
                int n = wn + ni * 8 + g;
                bf[ni][0] = Bs[kk + tg][n];
                bf[ni][1] = Bs[kk + tg + 4][n];
            }
#pragma unroll
            for (int mi = 0; mi < 4; mi++)
#pragma unroll
                for (int ni = 0; ni < 4; ni++)
                    mma_tf32(c[mi][ni][0], c[mi][ni][1], c[mi][ni][2], c[mi][ni][3],
                             af[mi][0], af[mi][1], af[mi][2], af[mi][3],
                             bf[ni][0], bf[ni][1]);
        }
    }

#pragma unroll
    for (int mi = 0; mi < 4; mi++) {
#pragma unroll
        for (int ni = 0; ni < 4; ni++) {
            int row = bm + wm + mi * 16 + g;
            int col = bn + wn + ni * 8 + 2 * tg;
            float v0 = c[mi][ni][0], v1 = c[mi][ni][1];
            float v2 = c[mi][ni][2], v3 = c[mi][ni][3];
            if (round_out) {
                v0 = __uint_as_float(f2tf32(v0));
                v1 = __uint_as_float(f2tf32(v1));
                v2 = __uint_as_float(f2tf32(v2));
                v3 = __uint_as_float(f2tf32(v3));
            }
            *(float2*)(C + (size_t)row * N + col)       = make_float2(v0, v1);
            *(float2*)(C + (size_t)(row + 8) * N + col) = make_float2(v2, v3);
        }
    }
}

// ---------------------------------------------------------------------------
// Tensor-core causal flash attention (tf32 mma.sync), v2:
//  - K/V double-buffered via cp.async (inputs pre-rounded to tf32 by GEMM)
//  - K natural [n][d] stride 68, V [k][n] stride 72: both fragment LDS
//    patterns are bank bijections; no transpose, no converts in the loop.
//  - __launch_bounds__(256,2): 2 blocks/SM.
//  - qt reversed so heaviest causal blocks are scheduled first.
// ---------------------------------------------------------------------------
#define PQ_STR 136
#define KN_STR 68
#define V_STR  72
#define FA_Q_U32   (64 * PQ_STR)                 // 8704
#define FA_K_U32   (64 * KN_STR)                 // 4352 per stage
#define FA_V_U32   (64 * V_STR)                  // 4608 per stage
#define FA_SMEM_U32 (FA_Q_U32 + 2*FA_K_U32 + 2*FA_V_U32)
#define FA_SMEM_B   (FA_SMEM_U32 * 4)            // 106496 B

__global__ __launch_bounds__(256, 2) void flash_attn_tc(const float* __restrict__ Qg,
                                                        const float* __restrict__ Kg,
                                                        const float* __restrict__ Vg,
                                                        float* __restrict__ Og)
{
    extern __shared__ uint32_t sm[];
    uint32_t* Qs = sm;                                  // [64][136], reused as Ps
    uint32_t* Ksb[2] = { sm + FA_Q_U32, sm + FA_Q_U32 + FA_K_U32 };
    uint32_t* Vsb[2] = { sm + FA_Q_U32 + 2*FA_K_U32,
                         sm + FA_Q_U32 + 2*FA_K_U32 + FA_V_U32 };

    const int qt   = (gridDim.x - 1) - blockIdx.x;      // heavy first
    const int bh   = blockIdx.y;
    const int b    = bh >> 4;
    const int h    = bh & 15;
    const int tid  = threadIdx.x;
    const int lane = tid & 31;
    const int warp = tid >> 5;
    const int g    = lane >> 2;
    const int tg   = lane & 3;
    const int m0   = warp * 16;
    const int q0   = qt * 128;

    const size_t base = (size_t)b * S_ * D_ + (size_t)h * DH_;
    const int nkt = 2 * qt + 2;

    // per-thread cp.async chunk mapping: 4 chunks per array per tile
    int crow[4], ccol[4];
#pragma unroll
    for (int it = 0; it < 4; it++) {
        int idx = it * 256 + tid;
        crow[it] = idx >> 4;          // 0..63
        ccol[it] = (idx & 15) * 4;    // float col, 16B chunks
    }

    // ---- issue loads for kt=0 ----
    {
        uint32_t ksa = smem_u32addr(Ksb[0]);
        uint32_t vsa = smem_u32addr(Vsb[0]);
#pragma unroll
        for (int it = 0; it < 4; it++) {
            cp_async16(ksa + (crow[it] * KN_STR + ccol[it]) * 4,
                       Kg + base + (size_t)crow[it] * D_ + ccol[it]);
            cp_async16(vsa + (crow[it] * V_STR + ccol[it]) * 4,
                       Vg + base + (size_t)crow[it] * D_ + ccol[it]);
        }
        asm volatile("cp.async.commit_group;");
    }

    // ---- load Q tile [128x64] -> Qs[d][m], scaled by 1/8 ----
#pragma unroll
    for (int it = 0; it < 8; it++) {
        int idx = it * 256 + tid;
        int r = (idx >> 2) & 127;
        int c = 4 * (idx & 3) + 16 * (idx >> 9);
        float4 t = *(const float4*)(Qg + base + (size_t)(q0 + r) * D_ + c);
        Qs[(c + 0) * PQ_STR + r] = f2tf32(t.x * 0.125f);
        Qs[(c + 1) * PQ_STR + r] = f2tf32(t.y * 0.125f);
        Qs[(c + 2) * PQ_STR + r] = f2tf32(t.z * 0.125f);
        Qs[(c + 3) * PQ_STR + r] = f2tf32(t.w * 0.125f);
    }
    __syncthreads();

    uint32_t qf[8][4];
#pragma unroll
    for (int kk2 = 0; kk2 < 8; kk2++) {
        qf[kk2][0] = Qs[(8 * kk2 + tg) * PQ_STR + m0 + g];
        qf[kk2][1] = Qs[(8 * kk2 + tg) * PQ_STR + m0 + g + 8];
        qf[kk2][2] = Qs[(8 * kk2 + tg + 4) * PQ_STR + m0 + g];
        qf[kk2][3] = Qs[(8 * kk2 + tg + 4) * PQ_STR + m0 + g + 8];
    }
    __syncthreads();   // Qs now reusable as Ps

    float o[8][4];
#pragma unroll
    for (int ni = 0; ni < 8; ni++)
#pragma unroll
        for (int f = 0; f < 4; f++) o[ni][f] = 0.f;
    float mrow[2] = {-1e30f, -1e30f};
    float lrow[2] = {0.f, 0.f};

    for (int kt = 0; kt < nkt; kt++) {
        const int buf = kt & 1;

        // issue next tile's loads
        if (kt + 1 < nkt) {
            const int k1 = (kt + 1) * 64;
            uint32_t ksa = smem_u32addr(Ksb[buf ^ 1]);
            uint32_t vsa = smem_u32addr(Vsb[buf ^ 1]);
#pragma unroll
            for (int it = 0; it < 4; it++) {
                cp_async16(ksa + (crow[it] * KN_STR + ccol[it]) * 4,
                           Kg + base + (size_t)(k1 + crow[it]) * D_ + ccol[it]);
                cp_async16(vsa + (crow[it] * V_STR + ccol[it]) * 4,
                           Vg + base + (size_t)(k1 + crow[it]) * D_ + ccol[it]);
            }
            asm volatile("cp.async.commit_group;");
            asm volatile("cp.async.wait_group 1;");
        } else {
            asm volatile("cp.async.wait_group 0;");
        }
        __syncthreads();

        const uint32_t* Ks = Ksb[buf];
        const uint32_t* Vs = Vsb[buf];
        const int k0 = kt * 64;

        // ---- S = (Q/8) K^T ----
        float s[8][4];
#pragma unroll
        for (int ni = 0; ni < 8; ni++) {
            s[ni][0] = s[ni][1] = s[ni][2] = s[ni][3] = 0.f;
            const uint32_t* kr = Ks + (ni * 8 + g) * KN_STR;
#pragma unroll
            for (int kk2 = 0; kk2 < 8; kk2++) {
                uint32_t b0 = kr[8 * kk2 + tg];
                uint32_t b1 = kr[8 * kk2 + tg + 4];
                mma_tf32(s[ni][0], s[ni][1], s[ni][2], s[ni][3],
                         qf[kk2][0], qf[kk2][1], qf[kk2][2], qf[kk2][3], b0, b1);
            }
        }

        // ---- causal mask (two diagonal tiles only) ----
        if (kt >= 2 * qt) {
            int row0 = q0 + m0 + g;
            int row1 = row0 + 8;
#pragma unroll
            for (int ni = 0; ni < 8; ni++) {
                int c0 = k0 + ni * 8 + 2 * tg;
                if (c0     > row0) s[ni][0] = -1e30f;
                if (c0 + 1 > row0) s[ni][1] = -1e30f;
                if (c0     > row1) s[ni][2] = -1e30f;
                if (c0 + 1 > row1) s[ni][3] = -1e30f;
            }
        }

        // ---- online softmax ----
#pragma unroll
        for (int r2 = 0; r2 < 2; r2++) {
            float mx = -1e30f;
#pragma unroll
            for (int ni = 0; ni < 8; ni++)
                mx = fmaxf(mx, fmaxf(s[ni][2 * r2], s[ni][2 * r2 + 1]));
            mx = fmaxf(mx, __shfl_xor_sync(0xffffffffu, mx, 1));
            mx = fmaxf(mx, __shfl_xor_sync(0xffffffffu, mx, 2));
            float mnew  = fmaxf(mrow[r2], mx);
            float alpha = __expf(mrow[r2] - mnew);
            mrow[r2] = mnew;
            float rs = 0.f;
#pragma unroll
            for (int ni = 0; ni < 8; ni++) {
                float p0 = __expf(s[ni][2 * r2]     - mnew);
                float p1 = __expf(s[ni][2 * r2 + 1] - mnew);
                s[ni][2 * r2] = p0; s[ni][2 * r2 + 1] = p1;
                rs += p0 + p1;
            }
            rs += __shfl_xor_sync(0xffffffffu, rs, 1);
            rs += __shfl_xor_sync(0xffffffffu, rs, 2);
            lrow[r2] = lrow[r2] * alpha + rs;
#pragma unroll
            for (int ni = 0; ni < 8; ni++) {
                o[ni][2 * r2]     *= alpha;
                o[ni][2 * r2 + 1] *= alpha;
            }
        }

        // ---- stage P (per-warp-private m columns) ----
        uint32_t* Ps = Qs;
#pragma unroll
        for (int ni = 0; ni < 8; ni++) {
            int c0 = ni * 8 + 2 * tg;
            Ps[(c0)     * PQ_STR + m0 + g]     = f2tf32(s[ni][0]);
            Ps[(c0 + 1) * PQ_STR + m0 + g]     = f2tf32(s[ni][1]);
            Ps[(c0)     * PQ_STR + m0 + g + 8] = f2tf32(s[ni][2]);
            Ps[(c0 + 1) * PQ_STR + m0 + g + 8] = f2tf32(s[ni][3]);
        }
        __syncwarp();

        // ---- O += P V ----
#pragma unroll
        for (int kk2 = 0; kk2 < 8; kk2++) {
            uint32_t a0 = Ps[(8 * kk2 + tg) * PQ_STR + m0 + g];
            uint32_t a1 = Ps[(8 * kk2 + tg) * PQ_STR + m0 + g + 8];
            uint32_t a2 = Ps[(8 * kk2 + tg + 4) * PQ_STR + m0 + g];
            uint32_t a3 = Ps[(8 * kk2 + tg + 4) * PQ_STR + m0 + g + 8];
#pragma unroll
            for (int ni = 0; ni < 8; ni++) {
                uint32_t b0 = Vs[(8 * kk2 + tg) * V_STR + ni * 8 + g];
                uint32_t b1 = Vs[(8 * kk2 + tg + 4) * V_STR + ni * 8 + g];
                mma_tf32(o[ni][0], o[ni][1], o[ni][2], o[ni][3], a0, a1, a2, a3, b0, b1);
            }
        }
        __syncthreads();   // protect buffers before next issue
    }

    // ---- epilogue ----
    const float inv0 = 1.f / lrow[0];
    const float inv1 = 1.f / lrow[1];
    const int row0 = q0 + m0 + g;
#pragma unroll
    for (int ni = 0; ni < 8; ni++) {
        int col = ni * 8 + 2 * tg;
        *(float2*)(Og + base + (size_t)row0 * D_ + col) =
            make_float2(o[ni][0] * inv0, o[ni][1] * inv0);
        *(float2*)(Og + base + (size_t)(row0 + 8) * D_ + col) =
            make_float2(o[ni][2] * inv1, o[ni][3] * inv1);
    }
}

// ---------------------------------------------------------------------------
extern "C" void kernel_launch(void* const* d_in, const int* in_sizes, int n_in,
                              void* d_out, int out_size)
{
    const float* x  = (const float*)d_in[0];
    const float* Wq = (const float*)d_in[1];
    const float* Wk = (const float*)d_in[2];
    const float* Wv = (const float*)d_in[3];
    const float* Wo = (const float*)d_in[4];
    float* out = (float*)d_out;

    float *q, *k, *v, *o;
    cudaGetSymbolAddress((void**)&q, g_q);
    cudaGetSymbolAddress((void**)&k, g_k);
    cudaGetSymbolAddress((void**)&v, g_v);
    cudaGetSymbolAddress((void**)&o, g_o);

    static bool attr_set = false;
    if (!attr_set) {
        cudaFuncSetAttribute(flash_attn_tc,
                             cudaFuncAttributeMaxDynamicSharedMemorySize, FA_SMEM_B);
        attr_set = true;
    }

    // Fused QKV projection (tf32-rounded outputs)
    gemm_nt_tf32<<<dim3(D_ / 128, MTOT / 128, 3), 256>>>(x, Wq, Wk, Wv, q, k, v, 1);

    flash_attn_tc<<<dim3(S_ / 128, B_ * H_), 256, FA_SMEM_B>>>(q, k, v, o);

    // Output projection (full fp32 out)
    gemm_nt_tf32<<<dim3(D_ / 128, MTOT / 128, 1), 256>>>(o, Wo, Wo, Wo, out, out, out, 0);
}

// round 6
// speedup vs baseline: 3.4761x; 1.2396x over previous
#include <cuda_runtime.h>
#include <cstdint>

#define B_    2
#define S_    2048
#define D_    1024
#define H_    16
#define DH_   64
#define MTOT  (B_ * S_)

__device__ float g_q[(size_t)MTOT * D_];
__device__ float g_k[(size_t)MTOT * D_];
__device__ float g_v[(size_t)MTOT * D_];
__device__ float g_o[(size_t)MTOT * D_];
// tf32-pre-rounded copies of x and the four weights
__device__ float g_xc[(size_t)MTOT * D_];
__device__ float g_wc[4][(size_t)D_ * D_];

// ---------------------------------------------------------------------------
__device__ __forceinline__ uint32_t f2tf32(float x) {
    uint32_t t;
    asm("cvt.rna.tf32.f32 %0, %1;" : "=r"(t) : "f"(x));
    return t;
}

__device__ __forceinline__ void mma_tf32(float& c0, float& c1, float& c2, float& c3,
                                         uint32_t a0, uint32_t a1, uint32_t a2, uint32_t a3,
                                         uint32_t b0, uint32_t b1) {
    asm volatile(
        "mma.sync.aligned.m16n8k8.row.col.f32.tf32.tf32.f32 "
        "{%0,%1,%2,%3}, {%4,%5,%6,%7}, {%8,%9}, {%0,%1,%2,%3};"
        : "+f"(c0), "+f"(c1), "+f"(c2), "+f"(c3)
        : "r"(a0), "r"(a1), "r"(a2), "r"(a3), "r"(b0), "r"(b1));
}

__device__ __forceinline__ void cp_async16(uint32_t saddr, const void* g) {
    asm volatile("cp.async.cg.shared.global [%0], [%1], 16;" :: "r"(saddr), "l"(g));
}
__device__ __forceinline__ uint32_t smem_u32addr(const void* p) {
    uint32_t a;
    asm("{ .reg .u64 t; cvta.to.shared.u64 t, %1; cvt.u32.u64 %0, t; }" : "=r"(a) : "l"(p));
    return a;
}

// ---------------------------------------------------------------------------
// Pre-convert: round 1M-float chunks to tf32 (rna). 8 chunks: x(4) + 4 weights.
// ---------------------------------------------------------------------------
__global__ __launch_bounds__(256) void cvt_tf32_kernel(const float* __restrict__ x,
                                                       const float* __restrict__ w0,
                                                       const float* __restrict__ w1,
                                                       const float* __restrict__ w2,
                                                       const float* __restrict__ w3)
{
    const size_t CH = (size_t)1024 * 1024;
    int z = blockIdx.z;
    const float* src;
    float* dst;
    if (z < 4)      { src = x  + z * CH;       dst = g_xc      + z * CH; }
    else            { src = (z==4?w0:z==5?w1:z==6?w2:w3); dst = g_wc[z-4]; }

    size_t i = ((size_t)blockIdx.x * 256 + threadIdx.x) * 4;
    float4 t = *(const float4*)(src + i);
    uint4 r;
    r.x = f2tf32(t.x); r.y = f2tf32(t.y); r.z = f2tf32(t.z); r.w = f2tf32(t.w);
    *(uint4*)(dst + i) = r;
}

// ---------------------------------------------------------------------------
// GEMM v2 (NT): C = A[M,K] * W[N,K]^T, inputs pre-rounded to tf32.
// 128x128 tile, BK=32, cp.async 2-stage double buffer, stride 36 smem
// ([m][k] / [n][k] natural layouts; 36 = 4 mod 32 -> fragment LDS bank
// bijection 4g+tg). round_out=1 stores tf32-rounded C (feeds flash/proj).
// ---------------------------------------------------------------------------
#define GK    32
#define GSTR  36
#define GT_U32   (128 * GSTR)                 // 4608 per array per stage
#define G_SMEM_U32 (4 * GT_U32)               // A0,B0,A1,B1
#define G_SMEM_B   (G_SMEM_U32 * 4)           // 73728 B

__global__ __launch_bounds__(256, 2) void gemm_nt_tf32(const float* __restrict__ A,
                                                       const float* __restrict__ W0,
                                                       const float* __restrict__ W1,
                                                       const float* __restrict__ W2,
                                                       float* __restrict__ C0,
                                                       float* __restrict__ C1,
                                                       float* __restrict__ C2,
                                                       int round_out)
{
    constexpr int N = D_;
    constexpr int K = D_;

    const float* W = (blockIdx.z == 0) ? W0 : (blockIdx.z == 1) ? W1 : W2;
    float*       C = (blockIdx.z == 0) ? C0 : (blockIdx.z == 1) ? C1 : C2;

    extern __shared__ uint32_t sg[];
    uint32_t* Asb[2] = { sg,              sg + 2 * GT_U32 };
    uint32_t* Bsb[2] = { sg + GT_U32,     sg + 3 * GT_U32 };

    const int tid  = threadIdx.x;
    const int bm   = blockIdx.y * 128;
    const int bn   = blockIdx.x * 128;
    const int lane = tid & 31;
    const int warp = tid >> 5;
    const int g    = lane >> 2;
    const int tg   = lane & 3;
    const int wm   = (warp >> 2) * 64;
    const int wn   = (warp & 3) * 32;

    // cp.async mapping: 4 chunks per thread per array (1024 chunks = 128x8)
    int crow[4], ccol[4];
#pragma unroll
    for (int it = 0; it < 4; it++) {
        int idx = it * 256 + tid;
        crow[it] = idx >> 3;          // 0..127
        ccol[it] = (idx & 7) * 4;     // 0..28
    }

    const float* Abase = A + (size_t)bm * K;
    const float* Wbase = W + (size_t)bn * K;

    // prologue: issue tile 0
    {
        uint32_t asa = smem_u32addr(Asb[0]);
        uint32_t bsa = smem_u32addr(Bsb[0]);
#pragma unroll
        for (int it = 0; it < 4; it++) {
            cp_async16(asa + (crow[it] * GSTR + ccol[it]) * 4,
                       Abase + (size_t)crow[it] * K + ccol[it]);
            cp_async16(bsa + (crow[it] * GSTR + ccol[it]) * 4,
                       Wbase + (size_t)crow[it] * K + ccol[it]);
        }
        asm volatile("cp.async.commit_group;");
    }

    float c[4][4][4];
#pragma unroll
    for (int mi = 0; mi < 4; mi++)
#pragma unroll
        for (int ni = 0; ni < 4; ni++)
#pragma unroll
            for (int f = 0; f < 4; f++) c[mi][ni][f] = 0.f;

    const int NT = K / GK;   // 32
    for (int t = 0; t < NT; t++) {
        const int buf = t & 1;
        if (t + 1 < NT) {
            const int k1 = (t + 1) * GK;
            uint32_t asa = smem_u32addr(Asb[buf ^ 1]);
            uint32_t bsa = smem_u32addr(Bsb[buf ^ 1]);
#pragma unroll
            for (int it = 0; it < 4; it++) {
                cp_async16(asa + (crow[it] * GSTR + ccol[it]) * 4,
                           Abase + (size_t)crow[it] * K + k1 + ccol[it]);
                cp_async16(bsa + (crow[it] * GSTR + ccol[it]) * 4,
                           Wbase + (size_t)crow[it] * K + k1 + ccol[it]);
            }
            asm volatile("cp.async.commit_group;");
            asm volatile("cp.async.wait_group 1;");
        } else {
            asm volatile("cp.async.wait_group 0;");
        }
        __syncthreads();

        const uint32_t* As = Asb[buf];
        const uint32_t* Bs = Bsb[buf];

#pragma unroll
        for (int kk = 0; kk < GK; kk += 8) {
            uint32_t af[4][4], bf[4][2];
#pragma unroll
            for (int mi = 0; mi < 4; mi++) {
                const uint32_t* ar = As + (wm + mi * 16 + g) * GSTR + kk;
                af[mi][0] = ar[tg];
                af[mi][1] = ar[8 * GSTR + tg];
                af[mi][2] = ar[tg + 4];
                af[mi][3] = ar[8 * GSTR + tg + 4];
            }
#pragma unroll
            for (int ni = 0; ni < 4; ni++) {
                const uint32_t* br = Bs + (wn + ni * 8 + g) * GSTR + kk;
                bf[ni][0] = br[tg];
                bf[ni][1] = br[tg + 4];
            }
#pragma unroll
            for (int mi = 0; mi < 4; mi++)
#pragma unroll
                for (int ni = 0; ni < 4; ni++)
                    mma_tf32(c[mi][ni][0], c[mi][ni][1], c[mi][ni][2], c[mi][ni][3],
                             af[mi][0], af[mi][1], af[mi][2], af[mi][3],
                             bf[ni][0], bf[ni][1]);
        }
        __syncthreads();   // computes done before next issue overwrites buf^1
    }

#pragma unroll
    for (int mi = 0; mi < 4; mi++) {
#pragma unroll
        for (int ni = 0; ni < 4; ni++) {
            int row = bm + wm + mi * 16 + g;
            int col = bn + wn + ni * 8 + 2 * tg;
            float v0 = c[mi][ni][0], v1 = c[mi][ni][1];
            float v2 = c[mi][ni][2], v3 = c[mi][ni][3];
            if (round_out) {
                v0 = __uint_as_float(f2tf32(v0));
                v1 = __uint_as_float(f2tf32(v1));
                v2 = __uint_as_float(f2tf32(v2));
                v3 = __uint_as_float(f2tf32(v3));
            }
            *(float2*)(C + (size_t)row * N + col)       = make_float2(v0, v1);
            *(float2*)(C + (size_t)(row + 8) * N + col) = make_float2(v2, v3);
        }
    }
}

// ---------------------------------------------------------------------------
// Tensor-core causal flash attention (unchanged core; epilogue now writes
// tf32-rounded O so the projection GEMM can cp.async it directly).
// ---------------------------------------------------------------------------
#define PQ_STR 136
#define KN_STR 68
#define V_STR  72
#define FA_Q_U32   (64 * PQ_STR)
#define FA_K_U32   (64 * KN_STR)
#define FA_V_U32   (64 * V_STR)
#define FA_SMEM_U32 (FA_Q_U32 + 2*FA_K_U32 + 2*FA_V_U32)
#define FA_SMEM_B   (FA_SMEM_U32 * 4)

__global__ __launch_bounds__(256, 2) void flash_attn_tc(const float* __restrict__ Qg,
                                                        const float* __restrict__ Kg,
                                                        const float* __restrict__ Vg,
                                                        float* __restrict__ Og)
{
    extern __shared__ uint32_t sm[];
    uint32_t* Qs = sm;
    uint32_t* Ksb[2] = { sm + FA_Q_U32, sm + FA_Q_U32 + FA_K_U32 };
    uint32_t* Vsb[2] = { sm + FA_Q_U32 + 2*FA_K_U32,
                         sm + FA_Q_U32 + 2*FA_K_U32 + FA_V_U32 };

    const int qt   = (gridDim.x - 1) - blockIdx.x;
    const int bh   = blockIdx.y;
    const int b    = bh >> 4;
    const int h    = bh & 15;
    const int tid  = threadIdx.x;
    const int lane = tid & 31;
    const int warp = tid >> 5;
    const int g    = lane >> 2;
    const int tg   = lane & 3;
    const int m0   = warp * 16;
    const int q0   = qt * 128;

    const size_t base = (size_t)b * S_ * D_ + (size_t)h * DH_;
    const int nkt = 2 * qt + 2;

    int crow[4], ccol[4];
#pragma unroll
    for (int it = 0; it < 4; it++) {
        int idx = it * 256 + tid;
        crow[it] = idx >> 4;
        ccol[it] = (idx & 15) * 4;
    }

    {
        uint32_t ksa = smem_u32addr(Ksb[0]);
        uint32_t vsa = smem_u32addr(Vsb[0]);
#pragma unroll
        for (int it = 0; it < 4; it++) {
            cp_async16(ksa + (crow[it] * KN_STR + ccol[it]) * 4,
                       Kg + base + (size_t)crow[it] * D_ + ccol[it]);
            cp_async16(vsa + (crow[it] * V_STR + ccol[it]) * 4,
                       Vg + base + (size_t)crow[it] * D_ + ccol[it]);
        }
        asm volatile("cp.async.commit_group;");
    }

#pragma unroll
    for (int it = 0; it < 8; it++) {
        int idx = it * 256 + tid;
        int r = (idx >> 2) & 127;
        int c = 4 * (idx & 3) + 16 * (idx >> 9);
        float4 t = *(const float4*)(Qg + base + (size_t)(q0 + r) * D_ + c);
        Qs[(c + 0) * PQ_STR + r] = f2tf32(t.x * 0.125f);
        Qs[(c + 1) * PQ_STR + r] = f2tf32(t.y * 0.125f);
        Qs[(c + 2) * PQ_STR + r] = f2tf32(t.z * 0.125f);
        Qs[(c + 3) * PQ_STR + r] = f2tf32(t.w * 0.125f);
    }
    __syncthreads();

    uint32_t qf[8][4];
#pragma unroll
    for (int kk2 = 0; kk2 < 8; kk2++) {
        qf[kk2][0] = Qs[(8 * kk2 + tg) * PQ_STR + m0 + g];
        qf[kk2][1] = Qs[(8 * kk2 + tg) * PQ_STR + m0 + g + 8];
        qf[kk2][2] = Qs[(8 * kk2 + tg + 4) * PQ_STR + m0 + g];
        qf[kk2][3] = Qs[(8 * kk2 + tg + 4) * PQ_STR + m0 + g + 8];
    }
    __syncthreads();

    float o[8][4];
#pragma unroll
    for (int ni = 0; ni < 8; ni++)
#pragma unroll
        for (int f = 0; f < 4; f++) o[ni][f] = 0.f;
    float mrow[2] = {-1e30f, -1e30f};
    float lrow[2] = {0.f, 0.f};

    for (int kt = 0; kt < nkt; kt++) {
        const int buf = kt & 1;

        if (kt + 1 < nkt) {
            const int k1 = (kt + 1) * 64;
            uint32_t ksa = smem_u32addr(Ksb[buf ^ 1]);
            uint32_t vsa = smem_u32addr(Vsb[buf ^ 1]);
#pragma unroll
            for (int it = 0; it < 4; it++) {
                cp_async16(ksa + (crow[it] * KN_STR + ccol[it]) * 4,
                           Kg + base + (size_t)(k1 + crow[it]) * D_ + ccol[it]);
                cp_async16(vsa + (crow[it] * V_STR + ccol[it]) * 4,
                           Vg + base + (size_t)(k1 + crow[it]) * D_ + ccol[it]);
            }
            asm volatile("cp.async.commit_group;");
            asm volatile("cp.async.wait_group 1;");
        } else {
            asm volatile("cp.async.wait_group 0;");
        }
        __syncthreads();

        const uint32_t* Ks = Ksb[buf];
        const uint32_t* Vs = Vsb[buf];
        const int k0 = kt * 64;

        float s[8][4];
#pragma unroll
        for (int ni = 0; ni < 8; ni++) {
            s[ni][0] = s[ni][1] = s[ni][2] = s[ni][3] = 0.f;
            const uint32_t* kr = Ks + (ni * 8 + g) * KN_STR;
#pragma unroll
            for (int kk2 = 0; kk2 < 8; kk2++) {
                uint32_t b0 = kr[8 * kk2 + tg];
                uint32_t b1 = kr[8 * kk2 + tg + 4];
                mma_tf32(s[ni][0], s[ni][1], s[ni][2], s[ni][3],
                         qf[kk2][0], qf[kk2][1], qf[kk2][2], qf[kk2][3], b0, b1);
            }
        }

        if (kt >= 2 * qt) {
            int row0 = q0 + m0 + g;
            int row1 = row0 + 8;
#pragma unroll
            for (int ni = 0; ni < 8; ni++) {
                int c0 = k0 + ni * 8 + 2 * tg;
                if (c0     > row0) s[ni][0] = -1e30f;
                if (c0 + 1 > row0) s[ni][1] = -1e30f;
                if (c0     > row1) s[ni][2] = -1e30f;
                if (c0 + 1 > row1) s[ni][3] = -1e30f;
            }
        }

#pragma unroll
        for (int r2 = 0; r2 < 2; r2++) {
            float mx = -1e30f;
#pragma unroll
            for (int ni = 0; ni < 8; ni++)
                mx = fmaxf(mx, fmaxf(s[ni][2 * r2], s[ni][2 * r2 + 1]));
            mx = fmaxf(mx, __shfl_xor_sync(0xffffffffu, mx, 1));
            mx = fmaxf(mx, __shfl_xor_sync(0xffffffffu, mx, 2));
            float mnew  = fmaxf(mrow[r2], mx);
            float alpha = __expf(mrow[r2] - mnew);
            mrow[r2] = mnew;
            float rs = 0.f;
#pragma unroll
            for (int ni = 0; ni < 8; ni++) {
                float p0 = __expf(s[ni][2 * r2]     - mnew);
                float p1 = __expf(s[ni][2 * r2 + 1] - mnew);
                s[ni][2 * r2] = p0; s[ni][2 * r2 + 1] = p1;
                rs += p0 + p1;
            }
            rs += __shfl_xor_sync(0xffffffffu, rs, 1);
            rs += __shfl_xor_sync(0xffffffffu, rs, 2);
            lrow[r2] = lrow[r2] * alpha + rs;
#pragma unroll
            for (int ni = 0; ni < 8; ni++) {
                o[ni][2 * r2]     *= alpha;
                o[ni][2 * r2 + 1] *= alpha;
            }
        }

        uint32_t* Ps = Qs;
#pragma unroll
        for (int ni = 0; ni < 8; ni++) {
            int c0 = ni * 8 + 2 * tg;
            Ps[(c0)     * PQ_STR + m0 + g]     = f2tf32(s[ni][0]);
            Ps[(c0 + 1) * PQ_STR + m0 + g]     = f2tf32(s[ni][1]);
            Ps[(c0)     * PQ_STR + m0 + g + 8] = f2tf32(s[ni][2]);
            Ps[(c0 + 1) * PQ_STR + m0 + g + 8] = f2tf32(s[ni][3]);
        }
        __syncwarp();

#pragma unroll
        for (int kk2 = 0; kk2 < 8; kk2++) {
            uint32_t a0 = Ps[(8 * kk2 + tg) * PQ_STR + m0 + g];
            uint32_t a1 = Ps[(8 * kk2 + tg) * PQ_STR + m0 + g + 8];
            uint32_t a2 = Ps[(8 * kk2 + tg + 4) * PQ_STR + m0 + g];
            uint32_t a3 = Ps[(8 * kk2 + tg + 4) * PQ_STR + m0 + g + 8];
#pragma unroll
            for (int ni = 0; ni < 8; ni++) {
                uint32_t b0 = Vs[(8 * kk2 + tg) * V_STR + ni * 8 + g];
                uint32_t b1 = Vs[(8 * kk2 + tg + 4) * V_STR + ni * 8 + g];
                mma_tf32(o[ni][0], o[ni][1], o[ni][2], o[ni][3], a0, a1, a2, a3, b0, b1);
            }
        }
        __syncthreads();
    }

    const float inv0 = 1.f / lrow[0];
    const float inv1 = 1.f / lrow[1];
    const int row0 = q0 + m0 + g;
#pragma unroll
    for (int ni = 0; ni < 8; ni++) {
        int col = ni * 8 + 2 * tg;
        float2 w0, w1;
        w0.x = __uint_as_float(f2tf32(o[ni][0] * inv0));
        w0.y = __uint_as_float(f2tf32(o[ni][1] * inv0));
        w1.x = __uint_as_float(f2tf32(o[ni][2] * inv1));
        w1.y = __uint_as_float(f2tf32(o[ni][3] * inv1));
        *(float2*)(Og + base + (size_t)row0 * D_ + col)       = w0;
        *(float2*)(Og + base + (size_t)(row0 + 8) * D_ + col) = w1;
    }
}

// ---------------------------------------------------------------------------
extern "C" void kernel_launch(void* const* d_in, const int* in_sizes, int n_in,
                              void* d_out, int out_size)
{
    const float* x  = (const float*)d_in[0];
    const float* Wq = (const float*)d_in[1];
    const float* Wk = (const float*)d_in[2];
    const float* Wv = (const float*)d_in[3];
    const float* Wo = (const float*)d_in[4];
    float* out = (float*)d_out;

    float *q, *k, *v, *o, *xc, *wc;
    cudaGetSymbolAddress((void**)&q,  g_q);
    cudaGetSymbolAddress((void**)&k,  g_k);
    cudaGetSymbolAddress((void**)&v,  g_v);
    cudaGetSymbolAddress((void**)&o,  g_o);
    cudaGetSymbolAddress((void**)&xc, g_xc);
    cudaGetSymbolAddress((void**)&wc, g_wc);
    const size_t WSZ = (size_t)D_ * D_;

    static bool attr_set = false;
    if (!attr_set) {
        cudaFuncSetAttribute(flash_attn_tc,
                             cudaFuncAttributeMaxDynamicSharedMemorySize, FA_SMEM_B);
        cudaFuncSetAttribute(gemm_nt_tf32,
                             cudaFuncAttributeMaxDynamicSharedMemorySize, G_SMEM_B);
        attr_set = true;
    }

    // 1) pre-round x + weights to tf32 (bit-identical to in-GEMM conversion)
    cvt_tf32_kernel<<<dim3(1024, 1, 8), 256>>>(x, Wq, Wk, Wv, Wo);

    // 2) fused QKV projection (tf32-rounded outputs)
    gemm_nt_tf32<<<dim3(D_ / 128, MTOT / 128, 3), 256, G_SMEM_B>>>(
        xc, wc + 0 * WSZ, wc + 1 * WSZ, wc + 2 * WSZ, q, k, v, 1);

    // 3) attention (writes tf32-rounded O)
    flash_attn_tc<<<dim3(S_ / 128, B_ * H_), 256, FA_SMEM_B>>>(q, k, v, o);

    // 4) output projection (full fp32 out)
    gemm_nt_tf32<<<dim3(D_ / 128, MTOT / 128, 1), 256, G_SMEM_B>>>(
        o, wc + 3 * WSZ, wc + 3 * WSZ, wc + 3 * WSZ, out, out, out, 0);
}

// round 8
// speedup vs baseline: 3.5877x; 1.0321x over previous
#include <cuda_runtime.h>
#include <cstdint>

#define B_    2
#define S_    2048
#define D_    1024
#define H_    16
#define DH_   64
#define MTOT  (B_ * S_)

__device__ float g_q[(size_t)MTOT * D_];
__device__ float g_k[(size_t)MTOT * D_];
__device__ float g_v[(size_t)MTOT * D_];
__device__ float g_o[(size_t)MTOT * D_];
__device__ float g_xc[(size_t)MTOT * D_];
__device__ float g_wc[4][(size_t)D_ * D_];

// ---------------------------------------------------------------------------
__device__ __forceinline__ uint32_t f2tf32(float x) {
    uint32_t t;
    asm("cvt.rna.tf32.f32 %0, %1;" : "=r"(t) : "f"(x));
    return t;
}

__device__ __forceinline__ void mma_tf32(float& c0, float& c1, float& c2, float& c3,
                                         uint32_t a0, uint32_t a1, uint32_t a2, uint32_t a3,
                                         uint32_t b0, uint32_t b1) {
    asm volatile(
        "mma.sync.aligned.m16n8k8.row.col.f32.tf32.tf32.f32 "
        "{%0,%1,%2,%3}, {%4,%5,%6,%7}, {%8,%9}, {%0,%1,%2,%3};"
        : "+f"(c0), "+f"(c1), "+f"(c2), "+f"(c3)
        : "r"(a0), "r"(a1), "r"(a2), "r"(a3), "r"(b0), "r"(b1));
}

__device__ __forceinline__ void cp_async16(uint32_t saddr, const void* g) {
    asm volatile("cp.async.cg.shared.global [%0], [%1], 16;" :: "r"(saddr), "l"(g));
}
__device__ __forceinline__ uint32_t smem_u32addr(const void* p) {
    uint32_t a;
    asm("{ .reg .u64 t; cvta.to.shared.u64 t, %1; cvt.u32.u64 %0, t; }" : "=r"(a) : "l"(p));
    return a;
}

// ---------------------------------------------------------------------------
// Pre-convert: round to tf32 (rna). 8 chunks of 1M floats: x(4) + 4 weights.
// ---------------------------------------------------------------------------
__global__ __launch_bounds__(256) void cvt_tf32_kernel(const float* __restrict__ x,
                                                       const float* __restrict__ w0,
                                                       const float* __restrict__ w1,
                                                       const float* __restrict__ w2,
                                                       const float* __restrict__ w3)
{
    const size_t CH = (size_t)1024 * 1024;
    int z = blockIdx.z;
    const float* src;
    float* dst;
    if (z < 4)      { src = x  + z * CH;       dst = g_xc      + z * CH; }
    else            { src = (z==4?w0:z==5?w1:z==6?w2:w3); dst = g_wc[z-4]; }

    size_t i = ((size_t)blockIdx.x * 256 + threadIdx.x) * 4;
    float4 t = *(const float4*)(src + i);
    uint4 r;
    r.x = f2tf32(t.x); r.y = f2tf32(t.y); r.z = f2tf32(t.z); r.w = f2tf32(t.w);
    *(uint4*)(dst + i) = r;
}

// ---------------------------------------------------------------------------
// GEMM v3 (NT): C = A[M,K] * W[N,K]^T, inputs pre-rounded to tf32.
// 128x128 tile, BK=32, cp.async 3-stage pipeline (prefetch distance 2),
// ONE __syncthreads per tile. Smem stride 36 ([m][k]/[n][k] natural).
// ---------------------------------------------------------------------------
#define GK    32
#define GSTR  36
#define GT_U32   (128 * GSTR)                  // 4608 per array
#define GSTAGE_U32 (2 * GT_U32)                // A + B per stage
#define G_SMEM_U32 (3 * GSTAGE_U32)
#define G_SMEM_B   (G_SMEM_U32 * 4)            // 110592 B

__global__ __launch_bounds__(256, 2) void gemm_nt_tf32(const float* __restrict__ A,
                                                       const float* __restrict__ W0,
                                                       const float* __restrict__ W1,
                                                       const float* __restrict__ W2,
                                                       float* __restrict__ C0,
                                                       float* __restrict__ C1,
                                                       float* __restrict__ C2,
                                                       int round_out)
{
    constexpr int N = D_;
    constexpr int K = D_;

    const float* W = (blockIdx.z == 0) ? W0 : (blockIdx.z == 1) ? W1 : W2;
    float*       C = (blockIdx.z == 0) ? C0 : (blockIdx.z == 1) ? C1 : C2;

    extern __shared__ uint32_t sg[];

    const int tid  = threadIdx.x;
    const int bm   = blockIdx.y * 128;
    const int bn   = blockIdx.x * 128;
    const int lane = tid & 31;
    const int warp = tid >> 5;
    const int g    = lane >> 2;
    const int tg   = lane & 3;
    const int wm   = (warp >> 2) * 64;
    const int wn   = (warp & 3) * 32;

    int crow[4], ccol[4];
#pragma unroll
    for (int it = 0; it < 4; it++) {
        int idx = it * 256 + tid;
        crow[it] = idx >> 3;
        ccol[it] = (idx & 7) * 4;
    }

    const float* Abase = A + (size_t)bm * K;
    const float* Wbase = W + (size_t)bn * K;
    const uint32_t sbase = smem_u32addr(sg);

    // prologue: issue tiles 0 and 1 into stages 0, 1
#pragma unroll
    for (int p = 0; p < 2; p++) {
        uint32_t asa = sbase + (p * GSTAGE_U32) * 4;
        uint32_t bsa = asa + GT_U32 * 4;
        int k0 = p * GK;
#pragma unroll
        for (int it = 0; it < 4; it++) {
            cp_async16(asa + (crow[it] * GSTR + ccol[it]) * 4,
                       Abase + (size_t)crow[it] * K + k0 + ccol[it]);
            cp_async16(bsa + (crow[it] * GSTR + ccol[it]) * 4,
                       Wbase + (size_t)crow[it] * K + k0 + ccol[it]);
        }
        asm volatile("cp.async.commit_group;");
    }

    float c[4][4][4];
#pragma unroll
    for (int mi = 0; mi < 4; mi++)
#pragma unroll
        for (int ni = 0; ni < 4; ni++)
#pragma unroll
            for (int f = 0; f < 4; f++) c[mi][ni][f] = 0.f;

    const int NT = K / GK;   // 32
    int st = 0;              // stage of tile t
    int st2 = 2;             // stage of tile t+2
    for (int t = 0; t < NT; t++) {
        if (t + 1 < NT) asm volatile("cp.async.wait_group 1;");
        else            asm volatile("cp.async.wait_group 0;");
        __syncthreads();

        // issue tile t+2 into stage st2 (its last reader finished at t-1,
        // which precedes the sync above in every warp's program order)
        if (t + 2 < NT) {
            uint32_t asa = sbase + (st2 * GSTAGE_U32) * 4;
            uint32_t bsa = asa + GT_U32 * 4;
            int k2 = (t + 2) * GK;
#pragma unroll
            for (int it = 0; it < 4; it++) {
                cp_async16(asa + (crow[it] * GSTR + ccol[it]) * 4,
                           Abase + (size_t)crow[it] * K + k2 + ccol[it]);
                cp_async16(bsa + (crow[it] * GSTR + ccol[it]) * 4,
                           Wbase + (size_t)crow[it] * K + k2 + ccol[it]);
            }
            asm volatile("cp.async.commit_group;");
        }

        const uint32_t* As = sg + st * GSTAGE_U32;
        const uint32_t* Bs = As + GT_U32;

#pragma unroll
        for (int kk = 0; kk < GK; kk += 8) {
            uint32_t af[4][4], bf[4][2];
#pragma unroll
            for (int mi = 0; mi < 4; mi++) {
                const uint32_t* ar = As + (wm + mi * 16 + g) * GSTR + kk;
                af[mi][0] = ar[tg];
                af[mi][1] = ar[8 * GSTR + tg];
                af[mi][2] = ar[tg + 4];
                af[mi][3] = ar[8 * GSTR + tg + 4];
            }
#pragma unroll
            for (int ni = 0; ni < 4; ni++) {
                const uint32_t* br = Bs + (wn + ni * 8 + g) * GSTR + kk;
                bf[ni][0] = br[tg];
                bf[ni][1] = br[tg + 4];
            }
#pragma unroll
            for (int mi = 0; mi < 4; mi++)
#pragma unroll
                for (int ni = 0; ni < 4; ni++)
                    mma_tf32(c[mi][ni][0], c[mi][ni][1], c[mi][ni][2], c[mi][ni][3],
                             af[mi][0], af[mi][1], af[mi][2], af[mi][3],
                             bf[ni][0], bf[ni][1]);
        }

        st  = (st  == 2) ? 0 : st + 1;
        st2 = (st2 == 2) ? 0 : st2 + 1;
    }

#pragma unroll
    for (int mi = 0; mi < 4; mi++) {
#pragma unroll
        for (int ni = 0; ni < 4; ni++) {
            int row = bm + wm + mi * 16 + g;
            int col = bn + wn + ni * 8 + 2 * tg;
            float v0 = c[mi][ni][0], v1 = c[mi][ni][1];
            float v2 = c[mi][ni][2], v3 = c[mi][ni][3];
            if (round_out) {
                v0 = __uint_as_float(f2tf32(v0));
                v1 = __uint_as_float(f2tf32(v1));
                v2 = __uint_as_float(f2tf32(v2));
                v3 = __uint_as_float(f2tf32(v3));
            }
            *(float2*)(C + (size_t)row * N + col)       = make_float2(v0, v1);
            *(float2*)(C + (size_t)(row + 8) * N + col) = make_float2(v2, v3);
        }
    }
}

// ---------------------------------------------------------------------------
// Tensor-core causal flash attention: single __syncthreads per K/V tile.
// ---------------------------------------------------------------------------
#define PQ_STR 136
#define KN_STR 68
#define V_STR  72
#define FA_Q_U32   (64 * PQ_STR)
#define FA_K_U32   (64 * KN_STR)
#define FA_V_U32   (64 * V_STR)
#define FA_SMEM_U32 (FA_Q_U32 + 2*FA_K_U32 + 2*FA_V_U32)
#define FA_SMEM_B   (FA_SMEM_U32 * 4)

__global__ __launch_bounds__(256, 2) void flash_attn_tc(const float* __restrict__ Qg,
                                                        const float* __restrict__ Kg,
                                                        const float* __restrict__ Vg,
                                                        float* __restrict__ Og)
{
    extern __shared__ uint32_t sm[];
    uint32_t* Qs = sm;
    uint32_t* Ksb[2] = { sm + FA_Q_U32, sm + FA_Q_U32 + FA_K_U32 };
    uint32_t* Vsb[2] = { sm + FA_Q_U32 + 2*FA_K_U32,
                         sm + FA_Q_U32 + 2*FA_K_U32 + FA_V_U32 };

    const int qt   = (gridDim.x - 1) - blockIdx.x;
    const int bh   = blockIdx.y;
    const int b    = bh >> 4;
    const int h    = bh & 15;
    const int tid  = threadIdx.x;
    const int lane = tid & 31;
    const int warp = tid >> 5;
    const int g    = lane >> 2;
    const int tg   = lane & 3;
    const int m0   = warp * 16;
    const int q0   = qt * 128;

    const size_t base = (size_t)b * S_ * D_ + (size_t)h * DH_;
    const int nkt = 2 * qt + 2;

    int crow[4], ccol[4];
#pragma unroll
    for (int it = 0; it < 4; it++) {
        int idx = it * 256 + tid;
        crow[it] = idx >> 4;
        ccol[it] = (idx & 15) * 4;
    }

    {
        uint32_t ksa = smem_u32addr(Ksb[0]);
        uint32_t vsa = smem_u32addr(Vsb[0]);
#pragma unroll
        for (int it = 0; it < 4; it++) {
            cp_async16(ksa + (crow[it] * KN_STR + ccol[it]) * 4,
                       Kg + base + (size_t)crow[it] * D_ + ccol[it]);
            cp_async16(vsa + (crow[it] * V_STR + ccol[it]) * 4,
                       Vg + base + (size_t)crow[it] * D_ + ccol[it]);
        }
        asm volatile("cp.async.commit_group;");
    }

#pragma unroll
    for (int it = 0; it < 8; it++) {
        int idx = it * 256 + tid;
        int r = (idx >> 2) & 127;
        int c = 4 * (idx & 3) + 16 * (idx >> 9);
        float4 t = *(const float4*)(Qg + base + (size_t)(q0 + r) * D_ + c);
        Qs[(c + 0) * PQ_STR + r] = f2tf32(t.x * 0.125f);
        Qs[(c + 1) * PQ_STR + r] = f2tf32(t.y * 0.125f);
        Qs[(c + 2) * PQ_STR + r] = f2tf32(t.z * 0.125f);
        Qs[(c + 3) * PQ_STR + r] = f2tf32(t.w * 0.125f);
    }
    __syncthreads();

    uint32_t qf[8][4];
#pragma unroll
    for (int kk2 = 0; kk2 < 8; kk2++) {
        qf[kk2][0] = Qs[(8 * kk2 + tg) * PQ_STR + m0 + g];
        qf[kk2][1] = Qs[(8 * kk2 + tg) * PQ_STR + m0 + g + 8];
        qf[kk2][2] = Qs[(8 * kk2 + tg + 4) * PQ_STR + m0 + g];
        qf[kk2][3] = Qs[(8 * kk2 + tg + 4) * PQ_STR + m0 + g + 8];
    }
    __syncthreads();

    float o[8][4];
#pragma unroll
    for (int ni = 0; ni < 8; ni++)
#pragma unroll
        for (int f = 0; f < 4; f++) o[ni][f] = 0.f;
    float mrow[2] = {-1e30f, -1e30f};
    float lrow[2] = {0.f, 0.f};

    for (int kt = 0; kt < nkt; kt++) {
        const int buf = kt & 1;

        asm volatile("cp.async.wait_group 0;");
        __syncthreads();

        // issue next tile into buf^1 (its last reader finished at kt-1,
        // before the sync every warp just passed)
        if (kt + 1 < nkt) {
            const int k1 = (kt + 1) * 64;
            uint32_t ksa = smem_u32addr(Ksb[buf ^ 1]);
            uint32_t vsa = smem_u32addr(Vsb[buf ^ 1]);
#pragma unroll
            for (int it = 0; it < 4; it++) {
                cp_async16(ksa + (crow[it] * KN_STR + ccol[it]) * 4,
                           Kg + base + (size_t)(k1 + crow[it]) * D_ + ccol[it]);
                cp_async16(vsa + (crow[it] * V_STR + ccol[it]) * 4,
                           Vg + base + (size_t)(k1 + crow[it]) * D_ + ccol[it]);
            }
            asm volatile("cp.async.commit_group;");
        }

        const uint32_t* Ks = Ksb[buf];
        const uint32_t* Vs = Vsb[buf];
        const int k0 = kt * 64;

        float s[8][4];
#pragma unroll
        for (int ni = 0; ni < 8; ni++) {
            s[ni][0] = s[ni][1] = s[ni][2] = s[ni][3] = 0.f;
            const uint32_t* kr = Ks + (ni * 8 + g) * KN_STR;
#pragma unroll
            for (int kk2 = 0; kk2 < 8; kk2++) {
                uint32_t b0 = kr[8 * kk2 + tg];
                uint32_t b1 = kr[8 * kk2 + tg + 4];
                mma_tf32(s[ni][0], s[ni][1], s[ni][2], s[ni][3],
                         qf[kk2][0], qf[kk2][1], qf[kk2][2], qf[kk2][3], b0, b1);
            }
        }

        if (kt >= 2 * qt) {
            int row0 = q0 + m0 + g;
            int row1 = row0 + 8;
#pragma unroll
            for (int ni = 0; ni < 8; ni++) {
                int c0 = k0 + ni * 8 + 2 * tg;
                if (c0     > row0) s[ni][0] = -1e30f;
                if (c0 + 1 > row0) s[ni][1] = -1e30f;
                if (c0     > row1) s[ni][2] = -1e30f;
                if (c0 + 1 > row1) s[ni][3] = -1e30f;
            }
        }

#pragma unroll
        for (int r2 = 0; r2 < 2; r2++) {
            float mx = -1e30f;
#pragma unroll
            for (int ni = 0; ni < 8; ni++)
                mx = fmaxf(mx, fmaxf(s[ni][2 * r2], s[ni][2 * r2 + 1]));
            mx = fmaxf(mx, __shfl_xor_sync(0xffffffffu, mx, 1));
            mx = fmaxf(mx, __shfl_xor_sync(0xffffffffu, mx, 2));
            float mnew  = fmaxf(mrow[r2], mx);
            float alpha = __expf(mrow[r2] - mnew);
            mrow[r2] = mnew;
            float rs = 0.f;
#pragma unroll
            for (int ni = 0; ni < 8; ni++) {
                float p0 = __expf(s[ni][2 * r2]     - mnew);
                float p1 = __expf(s[ni][2 * r2 + 1] - mnew);
                s[ni][2 * r2] = p0; s[ni][2 * r2 + 1] = p1;
                rs += p0 + p1;
            }
            rs += __shfl_xor_sync(0xffffffffu, rs, 1);
            rs += __shfl_xor_sync(0xffffffffu, rs, 2);
            lrow[r2] = lrow[r2] * alpha + rs;
#pragma unroll
            for (int ni = 0; ni < 8; ni++) {
                o[ni][2 * r2]     *= alpha;
                o[ni][2 * r2 + 1] *= alpha;
            }
        }

        uint32_t* Ps = Qs;
#pragma unroll
        for (int ni = 0; ni < 8; ni++) {
            int c0 = ni * 8 + 2 * tg;
            Ps[(c0)     * PQ_STR + m0 + g]     = f2tf32(s[ni][0]);
            Ps[(c0 + 1) * PQ_STR + m0 + g]     = f2tf32(s[ni][1]);
            Ps[(c0)     * PQ_STR + m0 + g + 8] = f2tf32(s[ni][2]);
            Ps[(c0 + 1) * PQ_STR + m0 + g + 8] = f2tf32(s[ni][3]);
        }
        __syncwarp();

#pragma unroll
        for (int kk2 = 0; kk2 < 8; kk2++) {
            uint32_t a0 = Ps[(8 * kk2 + tg) * PQ_STR + m0 + g];
            uint32_t a1 = Ps[(8 * kk2 + tg) * PQ_STR + m0 + g + 8];
            uint32_t a2 = Ps[(8 * kk2 + tg + 4) * PQ_STR + m0 + g];
            uint32_t a3 = Ps[(8 * kk2 + tg + 4) * PQ_STR + m0 + g + 8];
#pragma unroll
            for (int ni = 0; ni < 8; ni++) {
                uint32_t b0 = Vs[(8 * kk2 + tg) * V_STR + ni * 8 + g];
                uint32_t b1 = Vs[(8 * kk2 + tg + 4) * V_STR + ni * 8 + g];
                mma_tf32(o[ni][0], o[ni][1], o[ni][2], o[ni][3], a0, a1, a2, a3, b0, b1);
            }
        }
    }

    const float inv0 = 1.f / lrow[0];
    const float inv1 = 1.f / lrow[1];
    const int row0 = q0 + m0 + g;
#pragma unroll
    for (int ni = 0; ni < 8; ni++) {
        int col = ni * 8 + 2 * tg;
        float2 w0, w1;
        w0.x = __uint_as_float(f2tf32(o[ni][0] * inv0));
        w0.y = __uint_as_float(f2tf32(o[ni][1] * inv0));
        w1.x = __uint_as_float(f2tf32(o[ni][2] * inv1));
        w1.y = __uint_as_float(f2tf32(o[ni][3] * inv1));
        *(float2*)(Og + base + (size_t)row0 * D_ + col)       = w0;
        *(float2*)(Og + base + (size_t)(row0 + 8) * D_ + col) = w1;
    }
}

// ---------------------------------------------------------------------------
extern "C" void kernel_launch(void* const* d_in, const int* in_sizes, int n_in,
                              void* d_out, int out_size)
{
    const float* x  = (const float*)d_in[0];
    const float* Wq = (const float*)d_in[1];
    const float* Wk = (const float*)d_in[2];
    const float* Wv = (const float*)d_in[3];
    const float* Wo = (const float*)d_in[4];
    float* out = (float*)d_out;

    float *q, *k, *v, *o, *xc, *wc;
    cudaGetSymbolAddress((void**)&q,  g_q);
    cudaGetSymbolAddress((void**)&k,  g_k);
    cudaGetSymbolAddress((void**)&v,  g_v);
    cudaGetSymbolAddress((void**)&o,  g_o);
    cudaGetSymbolAddress((void**)&xc, g_xc);
    cudaGetSymbolAddress((void**)&wc, g_wc);
    const size_t WSZ = (size_t)D_ * D_;

    static bool attr_set = false;
    if (!attr_set) {
        cudaFuncSetAttribute(flash_attn_tc,
                             cudaFuncAttributeMaxDynamicSharedMemorySize, FA_SMEM_B);
        cudaFuncSetAttribute(gemm_nt_tf32,
                             cudaFuncAttributeMaxDynamicSharedMemorySize, G_SMEM_B);
        attr_set = true;
    }

    cvt_tf32_kernel<<<dim3(1024, 1, 8), 256>>>(x, Wq, Wk, Wv, Wo);

    gemm_nt_tf32<<<dim3(D_ / 128, MTOT / 128, 3), 256, G_SMEM_B>>>(
        xc, wc + 0 * WSZ, wc + 1 * WSZ, wc + 2 * WSZ, q, k, v, 1);

    flash_attn_tc<<<dim3(S_ / 128, B_ * H_), 256, FA_SMEM_B>>>(q, k, v, o);

    gemm_nt_tf32<<<dim3(D_ / 128, MTOT / 128, 1), 256, G_SMEM_B>>>(
        o, wc + 3 * WSZ, wc + 3 * WSZ, wc + 3 * WSZ, out, out, out, 0);
}

// round 10
// speedup vs baseline: 7.7433x; 2.1583x over previous
#include <cuda_runtime.h>
#include <cuda_fp16.h>
#include <cstdint>

#define B_    2
#define S_    2048
#define D_    1024
#define H_    16
#define DH_   64
#define MTOT  (B_ * S_)

// fp16 scratch
__device__ __half g_q[(size_t)MTOT * D_];
__device__ __half g_k[(size_t)MTOT * D_];
__device__ __half g_v[(size_t)MTOT * D_];
__device__ __half g_o[(size_t)MTOT * D_];
__device__ __half g_xh[(size_t)MTOT * D_];
__device__ __half g_wh[4][(size_t)D_ * D_];

// ---------------------------------------------------------------------------
__device__ __forceinline__ uint32_t pack_h2(float lo, float hi) {
    uint32_t u;
    asm("cvt.rn.f16x2.f32 %0, %1, %2;" : "=r"(u) : "f"(hi), "f"(lo));
    return u;
}

__device__ __forceinline__ void mma_f16(float& c0, float& c1, float& c2, float& c3,
                                        uint32_t a0, uint32_t a1, uint32_t a2, uint32_t a3,
                                        uint32_t b0, uint32_t b1) {
    asm volatile(
        "mma.sync.aligned.m16n8k16.row.col.f32.f16.f16.f32 "
        "{%0,%1,%2,%3}, {%4,%5,%6,%7}, {%8,%9}, {%0,%1,%2,%3};"
        : "+f"(c0), "+f"(c1), "+f"(c2), "+f"(c3)
        : "r"(a0), "r"(a1), "r"(a2), "r"(a3), "r"(b0), "r"(b1));
}

__device__ __forceinline__ void cp_async16(uint32_t saddr, const void* g) {
    asm volatile("cp.async.cg.shared.global [%0], [%1], 16;" :: "r"(saddr), "l"(g));
}
__device__ __forceinline__ uint32_t smem_u32addr(const void* p) {
    uint32_t a;
    asm("{ .reg .u64 t; cvta.to.shared.u64 t, %1; cvt.u32.u64 %0, t; }" : "=r"(a) : "l"(p));
    return a;
}
__device__ __forceinline__ void ldmatrix_x4_trans(uint32_t& r0, uint32_t& r1,
                                                  uint32_t& r2, uint32_t& r3,
                                                  uint32_t addr) {
    asm volatile("ldmatrix.sync.aligned.m8n8.x4.trans.shared.b16 {%0,%1,%2,%3}, [%4];"
                 : "=r"(r0), "=r"(r1), "=r"(r2), "=r"(r3) : "r"(addr));
}

// ---------------------------------------------------------------------------
// Pre-convert fp32 -> fp16. 8 chunks of 1M floats: x(4) + 4 weights.
// ---------------------------------------------------------------------------
__global__ __launch_bounds__(256) void cvt_h_kernel(const float* __restrict__ x,
                                                    const float* __restrict__ w0,
                                                    const float* __restrict__ w1,
                                                    const float* __restrict__ w2,
                                                    const float* __restrict__ w3)
{
    const size_t CH = (size_t)1024 * 1024;
    int z = blockIdx.z;
    const float* src;
    __half* dst;
    if (z < 4) { src = x + z * CH; dst = g_xh + z * CH; }
    else       { src = (z==4?w0:z==5?w1:z==6?w2:w3); dst = g_wh[z-4]; }

    size_t i = ((size_t)blockIdx.x * 256 + threadIdx.x) * 4;
    float4 t = *(const float4*)(src + i);
    uint2 r;
    r.x = pack_h2(t.x, t.y);
    r.y = pack_h2(t.z, t.w);
    *(uint2*)(dst + i) = r;
}

// ---------------------------------------------------------------------------
// fp16 tensor-core GEMM (NT): C = A[M,K] * W[N,K]^T, A/W half, C half or float.
// 128x128 tile, BK=64 halves, 2-stage cp.async, single sync per tile.
// Smem [row][k] halves, stride 36 words (32 data + 4 pad; 36 = 4 mod 32 ->
// fragment LDS bank bijection 4g+tg).
// ---------------------------------------------------------------------------
#define GK    64
#define GSTRW 36
#define GT_U32     (128 * GSTRW)               // words per array
#define GSTAGE_U32 (2 * GT_U32)
#define G_SMEM_B   (2 * GSTAGE_U32 * 4)        // 73728 B

__global__ __launch_bounds__(256, 2) void gemm_h(const __half* __restrict__ A,
                                                 const __half* __restrict__ W0,
                                                 const __half* __restrict__ W1,
                                                 const __half* __restrict__ W2,
                                                 void* __restrict__ C0v,
                                                 void* __restrict__ C1v,
                                                 void* __restrict__ C2v,
                                                 int half_out)
{
    constexpr int N = D_;
    constexpr int K = D_;

    const __half* W = (blockIdx.z == 0) ? W0 : (blockIdx.z == 1) ? W1 : W2;
    void*         Cv = (blockIdx.z == 0) ? C0v : (blockIdx.z == 1) ? C1v : C2v;

    extern __shared__ uint32_t sg[];

    const int tid  = threadIdx.x;
    const int bm   = blockIdx.y * 128;
    const int bn   = blockIdx.x * 128;
    const int lane = tid & 31;
    const int warp = tid >> 5;
    const int g    = lane >> 2;
    const int tg   = lane & 3;
    const int wm   = (warp >> 2) * 64;
    const int wn   = (warp & 3) * 32;

    // cp.async: per array 128 rows x 8 chunks(16B) = 1024 chunks; 4/thread
    int crow[4], cc16[4];
#pragma unroll
    for (int it = 0; it < 4; it++) {
        int idx = it * 256 + tid;
        crow[it] = idx >> 3;
        cc16[it] = idx & 7;
    }

    const __half* Abase = A + (size_t)bm * K;
    const __half* Wbase = W + (size_t)bn * K;
    const uint32_t sb = smem_u32addr(sg);

    auto load_stage = [&](int s, int kf) {
        uint32_t asa = sb + (s * GSTAGE_U32) * 4;
        uint32_t bsa = asa + GT_U32 * 4;
#pragma unroll
        for (int it = 0; it < 4; it++) {
            uint32_t off = (uint32_t)(crow[it] * GSTRW + cc16[it] * 4) * 4;
            cp_async16(asa + off, Abase + (size_t)crow[it] * K + kf + cc16[it] * 8);
            cp_async16(bsa + off, Wbase + (size_t)crow[it] * K + kf + cc16[it] * 8);
        }
        asm volatile("cp.async.commit_group;");
    };

    load_stage(0, 0);

    float c[4][4][4];
#pragma unroll
    for (int mi = 0; mi < 4; mi++)
#pragma unroll
        for (int ni = 0; ni < 4; ni++)
#pragma unroll
            for (int f = 0; f < 4; f++) c[mi][ni][f] = 0.f;

    const int NT = K / GK;   // 16
    for (int t = 0; t < NT; t++) {
        asm volatile("cp.async.wait_group 0;");
        __syncthreads();

        if (t + 1 < NT) load_stage((t + 1) & 1, (t + 1) * GK);

        const uint32_t* As = sg + (t & 1) * GSTAGE_U32;
        const uint32_t* Bs = As + GT_U32;

#pragma unroll
        for (int ks = 0; ks < GK / 16; ks++) {   // 4 k16 steps
            uint32_t af[4][4], bf[4][2];
#pragma unroll
            for (int mi = 0; mi < 4; mi++) {
                const uint32_t* ar = As + (wm + mi * 16 + g) * GSTRW + ks * 8;
                af[mi][0] = ar[tg];
                af[mi][1] = ar[8 * GSTRW + tg];
                af[mi][2] = ar[tg + 4];
                af[mi][3] = ar[8 * GSTRW + tg + 4];
            }
#pragma unroll
            for (int ni = 0; ni < 4; ni++) {
                const uint32_t* br = Bs + (wn + ni * 8 + g) * GSTRW + ks * 8;
                bf[ni][0] = br[tg];
                bf[ni][1] = br[tg + 4];
            }
#pragma unroll
            for (int mi = 0; mi < 4; mi++)
#pragma unroll
                for (int ni = 0; ni < 4; ni++)
                    mma_f16(c[mi][ni][0], c[mi][ni][1], c[mi][ni][2], c[mi][ni][3],
                            af[mi][0], af[mi][1], af[mi][2], af[mi][3],
                            bf[ni][0], bf[ni][1]);
        }
    }

    if (half_out) {
        __half* C = (__half*)Cv;
#pragma unroll
        for (int mi = 0; mi < 4; mi++)
#pragma unroll
            for (int ni = 0; ni < 4; ni++) {
                int row = bm + wm + mi * 16 + g;
                int col = bn + wn + ni * 8 + 2 * tg;
                *(uint32_t*)(C + (size_t)row * N + col)       = pack_h2(c[mi][ni][0], c[mi][ni][1]);
                *(uint32_t*)(C + (size_t)(row + 8) * N + col) = pack_h2(c[mi][ni][2], c[mi][ni][3]);
            }
    } else {
        float* C = (float*)Cv;
#pragma unroll
        for (int mi = 0; mi < 4; mi++)
#pragma unroll
            for (int ni = 0; ni < 4; ni++) {
                int row = bm + wm + mi * 16 + g;
                int col = bn + wn + ni * 8 + 2 * tg;
                *(float2*)(C + (size_t)row * N + col)       = make_float2(c[mi][ni][0], c[mi][ni][1]);
                *(float2*)(C + (size_t)(row + 8) * N + col) = make_float2(c[mi][ni][2], c[mi][ni][3]);
            }
    }
}

// ---------------------------------------------------------------------------
// fp16 tensor-core causal flash attention.
// Block = 128 q-rows x one (b,h); 8 warps x 16 rows. Q fragments from global.
// K/V natural [token][d] halves in smem, stride 36 words (144 B rows).
// QK B-frags: direct word LDS. PV B-frags: ldmatrix.x4.trans.
// P: register-resident (S fragment == PV A fragment for m16n8k16).
// ---------------------------------------------------------------------------
#define FSTRW 36
#define FT_U32   (64 * FSTRW)                  // words per K or V tile
#define FA_SMEM_B (4 * FT_U32 * 4)             // 2 stages x (K+V) = 36864 B

__global__ __launch_bounds__(256, 2) void flash_attn_h(const __half* __restrict__ Qg,
                                                       const __half* __restrict__ Kg,
                                                       const __half* __restrict__ Vg,
                                                       __half* __restrict__ Og)
{
    extern __shared__ uint32_t sm[];
    // layout: [stage0: K | V][stage1: K | V]
    const uint32_t sb = smem_u32addr(sm);

    const int qt   = (gridDim.x - 1) - blockIdx.x;   // heavy blocks first
    const int bh   = blockIdx.y;
    const int b    = bh >> 4;
    const int h    = bh & 15;
    const int tid  = threadIdx.x;
    const int lane = tid & 31;
    const int warp = tid >> 5;
    const int g    = lane >> 2;
    const int tg   = lane & 3;
    const int m0   = warp * 16;
    const int q0   = qt * 128;

    const size_t base = (size_t)b * S_ * D_ + (size_t)h * DH_;
    const int nkt = 2 * qt + 2;

    // cp.async mapping: per array 64 rows x 8 chunks = 512; 2/thread
    int crow[2], cc16[2];
#pragma unroll
    for (int it = 0; it < 2; it++) {
        int idx = it * 256 + tid;
        crow[it] = idx >> 3;
        cc16[it] = idx & 7;
    }

    auto load_tile = [&](int s, int k0) {
        uint32_t ksa = sb + (s * 2 * FT_U32) * 4;
        uint32_t vsa = ksa + FT_U32 * 4;
#pragma unroll
        for (int it = 0; it < 2; it++) {
            uint32_t off = (uint32_t)(crow[it] * FSTRW + cc16[it] * 4) * 4;
            cp_async16(ksa + off, Kg + base + (size_t)(k0 + crow[it]) * D_ + cc16[it] * 8);
            cp_async16(vsa + off, Vg + base + (size_t)(k0 + crow[it]) * D_ + cc16[it] * 8);
        }
        asm volatile("cp.async.commit_group;");
    };

    load_tile(0, 0);

    // Q fragments straight from global (half pairs are 4B-aligned words)
    uint32_t qf[4][4];
    {
        const __half* qr0 = Qg + base + (size_t)(q0 + m0 + g) * D_;
        const __half* qr1 = qr0 + 8 * D_;
#pragma unroll
        for (int ks = 0; ks < 4; ks++) {
            qf[ks][0] = *(const uint32_t*)(qr0 + ks * 16 + 2 * tg);
            qf[ks][1] = *(const uint32_t*)(qr1 + ks * 16 + 2 * tg);
            qf[ks][2] = *(const uint32_t*)(qr0 + ks * 16 + 2 * tg + 8);
            qf[ks][3] = *(const uint32_t*)(qr1 + ks * 16 + 2 * tg + 8);
        }
    }

    float o[8][4];
#pragma unroll
    for (int ni = 0; ni < 8; ni++)
#pragma unroll
        for (int f = 0; f < 4; f++) o[ni][f] = 0.f;
    float mrow[2] = {-1e30f, -1e30f};
    float lrow[2] = {0.f, 0.f};

    for (int kt = 0; kt < nkt; kt++) {
        const int buf = kt & 1;

        asm volatile("cp.async.wait_group 0;");
        __syncthreads();

        if (kt + 1 < nkt) load_tile(buf ^ 1, (kt + 1) * 64);

        const uint32_t* Ks = sm + buf * 2 * FT_U32;
        const uint32_t  vsbase = sb + (buf * 2 * FT_U32 + FT_U32) * 4;
        const int k0 = kt * 64;

        // ---- S = Q K^T (scale applied after) ----
        float s[8][4];
#pragma unroll
        for (int ni = 0; ni < 8; ni++) {
            s[ni][0] = s[ni][1] = s[ni][2] = s[ni][3] = 0.f;
            const uint32_t* kr = Ks + (ni * 8 + g) * FSTRW;
#pragma unroll
            for (int ks = 0; ks < 4; ks++) {
                uint32_t b0 = kr[ks * 8 + tg];
                uint32_t b1 = kr[ks * 8 + tg + 4];
                mma_f16(s[ni][0], s[ni][1], s[ni][2], s[ni][3],
                        qf[ks][0], qf[ks][1], qf[ks][2], qf[ks][3], b0, b1);
            }
#pragma unroll
            for (int f = 0; f < 4; f++) s[ni][f] *= 0.125f;
        }

        // ---- causal mask (diagonal tiles only) ----
        if (kt >= 2 * qt) {
            int row0 = q0 + m0 + g;
            int row1 = row0 + 8;
#pragma unroll
            for (int ni = 0; ni < 8; ni++) {
                int c0 = k0 + ni * 8 + 2 * tg;
                if (c0     > row0) s[ni][0] = -1e30f;
                if (c0 + 1 > row0) s[ni][1] = -1e30f;
                if (c0     > row1) s[ni][2] = -1e30f;
                if (c0 + 1 > row1) s[ni][3] = -1e30f;
            }
        }

        // ---- online softmax ----
#pragma unroll
        for (int r2 = 0; r2 < 2; r2++) {
            float mx = -1e30f;
#pragma unroll
            for (int ni = 0; ni < 8; ni++)
                mx = fmaxf(mx, fmaxf(s[ni][2 * r2], s[ni][2 * r2 + 1]));
            mx = fmaxf(mx, __shfl_xor_sync(0xffffffffu, mx, 1));
            mx = fmaxf(mx, __shfl_xor_sync(0xffffffffu, mx, 2));
            float mnew  = fmaxf(mrow[r2], mx);
            float alpha = __expf(mrow[r2] - mnew);
            mrow[r2] = mnew;
            float rs = 0.f;
#pragma unroll
            for (int ni = 0; ni < 8; ni++) {
                float p0 = __expf(s[ni][2 * r2]     - mnew);
                float p1 = __expf(s[ni][2 * r2 + 1] - mnew);
                s[ni][2 * r2] = p0; s[ni][2 * r2 + 1] = p1;
                rs += p0 + p1;
            }
            rs += __shfl_xor_sync(0xffffffffu, rs, 1);
            rs += __shfl_xor_sync(0xffffffffu, rs, 2);
            lrow[r2] = lrow[r2] * alpha + rs;
#pragma unroll
            for (int ni = 0; ni < 8; ni++) {
                o[ni][2 * r2]     *= alpha;
                o[ni][2 * r2 + 1] *= alpha;
            }
        }

        // ---- O += P V : P packed in registers, V via ldmatrix.trans ----
#pragma unroll
        for (int ks = 0; ks < 4; ks++) {
            uint32_t a0 = pack_h2(s[2*ks][0],   s[2*ks][1]);
            uint32_t a1 = pack_h2(s[2*ks][2],   s[2*ks][3]);
            uint32_t a2 = pack_h2(s[2*ks+1][0], s[2*ks+1][1]);
            uint32_t a3 = pack_h2(s[2*ks+1][2], s[2*ks+1][3]);
            // lane address: token row = 16ks + (lane&15), d col block = nb*16 + 8*(lane>>4)
            uint32_t vrow = vsbase + (uint32_t)(16 * ks + (lane & 15)) * (FSTRW * 4)
                                   + (uint32_t)(lane >> 4) * 16;
#pragma unroll
            for (int nb = 0; nb < 4; nb++) {
                uint32_t r0, r1, r2, r3;
                ldmatrix_x4_trans(r0, r1, r2, r3, vrow + (uint32_t)nb * 32);
                mma_f16(o[2*nb][0],   o[2*nb][1],   o[2*nb][2],   o[2*nb][3],
                        a0, a1, a2, a3, r0, r1);
                mma_f16(o[2*nb+1][0], o[2*nb+1][1], o[2*nb+1][2], o[2*nb+1][3],
                        a0, a1, a2, a3, r2, r3);
            }
        }
    }

    // ---- epilogue (half output) ----
    const float inv0 = 1.f / lrow[0];
    const float inv1 = 1.f / lrow[1];
    const int row0 = q0 + m0 + g;
    __half* op0 = Og + base + (size_t)row0 * D_;
    __half* op1 = op0 + 8 * D_;
#pragma unroll
    for (int ni = 0; ni < 8; ni++) {
        int col = ni * 8 + 2 * tg;
        *(uint32_t*)(op0 + col) = pack_h2(o[ni][0] * inv0, o[ni][1] * inv0);
        *(uint32_t*)(op1 + col) = pack_h2(o[ni][2] * inv1, o[ni][3] * inv1);
    }
}

// ---------------------------------------------------------------------------
extern "C" void kernel_launch(void* const* d_in, const int* in_sizes, int n_in,
                              void* d_out, int out_size)
{
    const float* x  = (const float*)d_in[0];
    const float* Wq = (const float*)d_in[1];
    const float* Wk = (const float*)d_in[2];
    const float* Wv = (const float*)d_in[3];
    const float* Wo = (const float*)d_in[4];
    float* out = (float*)d_out;

    __half *q, *k, *v, *o, *xh, *wh;
    cudaGetSymbolAddress((void**)&q,  g_q);
    cudaGetSymbolAddress((void**)&k,  g_k);
    cudaGetSymbolAddress((void**)&v,  g_v);
    cudaGetSymbolAddress((void**)&o,  g_o);
    cudaGetSymbolAddress((void**)&xh, g_xh);
    cudaGetSymbolAddress((void**)&wh, g_wh);
    const size_t WSZ = (size_t)D_ * D_;

    static bool attr_set = false;
    if (!attr_set) {
        cudaFuncSetAttribute(flash_attn_h,
                             cudaFuncAttributeMaxDynamicSharedMemorySize, FA_SMEM_B);
        cudaFuncSetAttribute(gemm_h,
                             cudaFuncAttributeMaxDynamicSharedMemorySize, G_SMEM_B);
        attr_set = true;
    }

    // 1) fp32 -> fp16 inputs
    cvt_h_kernel<<<dim3(1024, 1, 8), 256>>>(x, Wq, Wk, Wv, Wo);

    // 2) fused QKV projection (half outputs)
    gemm_h<<<dim3(D_ / 128, MTOT / 128, 3), 256, G_SMEM_B>>>(
        xh, wh + 0 * WSZ, wh + 1 * WSZ, wh + 2 * WSZ, q, k, v, 1);

    // 3) flash attention (half output)
    flash_attn_h<<<dim3(S_ / 128, B_ * H_), 256, FA_SMEM_B>>>(q, k, v, o);

    // 4) output projection (float output)
    gemm_h<<<dim3(D_ / 128, MTOT / 128, 1), 256, G_SMEM_B>>>(
        o, wh + 3 * WSZ, wh + 3 * WSZ, wh + 3 * WSZ, out, out, out, 0);
}

// round 12
// speedup vs baseline: 7.9869x; 1.0315x over previous
#include <cuda_runtime.h>
#include <cuda_fp16.h>
#include <cstdint>

#define B_    2
#define S_    2048
#define D_    1024
#define H_    16
#define DH_   64
#define MTOT  (B_ * S_)

// fp16 scratch
__device__ __half g_q[(size_t)MTOT * D_];
__device__ __half g_k[(size_t)MTOT * D_];
__device__ __half g_v[(size_t)MTOT * D_];
__device__ __half g_o[(size_t)MTOT * D_];
__device__ __half g_xh[(size_t)MTOT * D_];
__device__ __half g_wh[4][(size_t)D_ * D_];

// ---------------------------------------------------------------------------
__device__ __forceinline__ uint32_t pack_h2(float lo, float hi) {
    uint32_t u;
    asm("cvt.rn.f16x2.f32 %0, %1, %2;" : "=r"(u) : "f"(hi), "f"(lo));
    return u;
}

__device__ __forceinline__ void mma_f16(float& c0, float& c1, float& c2, float& c3,
                                        uint32_t a0, uint32_t a1, uint32_t a2, uint32_t a3,
                                        uint32_t b0, uint32_t b1) {
    asm volatile(
        "mma.sync.aligned.m16n8k16.row.col.f32.f16.f16.f32 "
        "{%0,%1,%2,%3}, {%4,%5,%6,%7}, {%8,%9}, {%0,%1,%2,%3};"
        : "+f"(c0), "+f"(c1), "+f"(c2), "+f"(c3)
        : "r"(a0), "r"(a1), "r"(a2), "r"(a3), "r"(b0), "r"(b1));
}

__device__ __forceinline__ void cp_async16(uint32_t saddr, const void* g) {
    asm volatile("cp.async.cg.shared.global [%0], [%1], 16;" :: "r"(saddr), "l"(g));
}
__device__ __forceinline__ uint32_t smem_u32addr(const void* p) {
    uint32_t a;
    asm("{ .reg .u64 t; cvta.to.shared.u64 t, %1; cvt.u32.u64 %0, t; }" : "=r"(a) : "l"(p));
    return a;
}
__device__ __forceinline__ void ldmatrix_x4(uint32_t& r0, uint32_t& r1,
                                            uint32_t& r2, uint32_t& r3, uint32_t addr) {
    asm volatile("ldmatrix.sync.aligned.m8n8.x4.shared.b16 {%0,%1,%2,%3}, [%4];"
                 : "=r"(r0), "=r"(r1), "=r"(r2), "=r"(r3) : "r"(addr));
}
__device__ __forceinline__ void ldmatrix_x4_trans(uint32_t& r0, uint32_t& r1,
                                                  uint32_t& r2, uint32_t& r3, uint32_t addr) {
    asm volatile("ldmatrix.sync.aligned.m8n8.x4.trans.shared.b16 {%0,%1,%2,%3}, [%4];"
                 : "=r"(r0), "=r"(r1), "=r"(r2), "=r"(r3) : "r"(addr));
}

// ---------------------------------------------------------------------------
// Pre-convert fp32 -> fp16. 8 chunks of 1M floats: x(4) + 4 weights.
// ---------------------------------------------------------------------------
__global__ __launch_bounds__(256) void cvt_h_kernel(const float* __restrict__ x,
                                                    const float* __restrict__ w0,
                                                    const float* __restrict__ w1,
                                                    const float* __restrict__ w2,
                                                    const float* __restrict__ w3)
{
    const size_t CH = (size_t)1024 * 1024;
    int z = blockIdx.z;
    const float* src;
    __half* dst;
    if (z < 4) { src = x + z * CH; dst = g_xh + z * CH; }
    else       { src = (z==4?w0:z==5?w1:z==6?w2:w3); dst = g_wh[z-4]; }

    size_t i = ((size_t)blockIdx.x * 256 + threadIdx.x) * 4;
    float4 t = *(const float4*)(src + i);
    uint2 r;
    r.x = pack_h2(t.x, t.y);
    r.y = pack_h2(t.z, t.w);
    *(uint2*)(dst + i) = r;
}

// ---------------------------------------------------------------------------
// fp16 tensor-core GEMM (NT): C = A[M,K] * W[N,K]^T. ldmatrix fragment loads.
// 128x128 tile, BK=64 halves, 2-stage cp.async, single sync per tile.
// Smem [row][k] halves, stride 36 words; LDSM 8-row groups cover all 32 banks.
// ---------------------------------------------------------------------------
#define GK    64
#define GSTRW 36
#define GT_U32     (128 * GSTRW)
#define GSTAGE_U32 (2 * GT_U32)
#define G_SMEM_B   (2 * GSTAGE_U32 * 4)        // 73728 B

__global__ __launch_bounds__(256, 2) void gemm_h(const __half* __restrict__ A,
                                                 const __half* __restrict__ W0,
                                                 const __half* __restrict__ W1,
                                                 const __half* __restrict__ W2,
                                                 void* __restrict__ C0v,
                                                 void* __restrict__ C1v,
                                                 void* __restrict__ C2v,
                                                 int half_out)
{
    constexpr int N = D_;
    constexpr int K = D_;

    const __half* W = (blockIdx.z == 0) ? W0 : (blockIdx.z == 1) ? W1 : W2;
    void*         Cv = (blockIdx.z == 0) ? C0v : (blockIdx.z == 1) ? C1v : C2v;

    extern __shared__ uint32_t sg[];

    const int tid  = threadIdx.x;
    const int bm   = blockIdx.y * 128;
    const int bn   = blockIdx.x * 128;
    const int lane = tid & 31;
    const int warp = tid >> 5;
    const int g    = lane >> 2;
    const int tg   = lane & 3;
    const int wm   = (warp >> 2) * 64;
    const int wn   = (warp & 3) * 32;

    int crow[4], cc16[4];
#pragma unroll
    for (int it = 0; it < 4; it++) {
        int idx = it * 256 + tid;
        crow[it] = idx >> 3;
        cc16[it] = idx & 7;
    }

    const __half* Abase = A + (size_t)bm * K;
    const __half* Wbase = W + (size_t)bn * K;
    const uint32_t sb = smem_u32addr(sg);

    // ldmatrix per-lane address offsets (bytes, relative to tile base)
    const uint32_t a_lane_off =
        (uint32_t)((wm + (lane & 15)) * GSTRW + 4 * (lane >> 4)) * 4;
    const uint32_t b_lane_off =
        (uint32_t)((wn + (lane & 7) + 8 * (lane >> 4)) * GSTRW + 4 * ((lane >> 3) & 1)) * 4;

    auto load_stage = [&](int s, int kf) {
        uint32_t asa = sb + (s * GSTAGE_U32) * 4;
        uint32_t bsa = asa + GT_U32 * 4;
#pragma unroll
        for (int it = 0; it < 4; it++) {
            uint32_t off = (uint32_t)(crow[it] * GSTRW + cc16[it] * 4) * 4;
            cp_async16(asa + off, Abase + (size_t)crow[it] * K + kf + cc16[it] * 8);
            cp_async16(bsa + off, Wbase + (size_t)crow[it] * K + kf + cc16[it] * 8);
        }
        asm volatile("cp.async.commit_group;");
    };

    load_stage(0, 0);

    float c[4][4][4];
#pragma unroll
    for (int mi = 0; mi < 4; mi++)
#pragma unroll
        for (int ni = 0; ni < 4; ni++)
#pragma unroll
            for (int f = 0; f < 4; f++) c[mi][ni][f] = 0.f;

    const int NT = K / GK;   // 16
    for (int t = 0; t < NT; t++) {
        asm volatile("cp.async.wait_group 0;");
        __syncthreads();

        if (t + 1 < NT) load_stage((t + 1) & 1, (t + 1) * GK);

        const uint32_t As_a = sb + ((t & 1) * GSTAGE_U32) * 4;
        const uint32_t Bs_a = As_a + GT_U32 * 4;

#pragma unroll
        for (int ks = 0; ks < GK / 16; ks++) {   // 4 k16 steps
            uint32_t af[4][4], bf[4][2];
#pragma unroll
            for (int mi = 0; mi < 4; mi++)
                ldmatrix_x4(af[mi][0], af[mi][1], af[mi][2], af[mi][3],
                            As_a + a_lane_off + (uint32_t)(mi * 16 * GSTRW) * 4 + ks * 32);
#pragma unroll
            for (int nb = 0; nb < 2; nb++)
                ldmatrix_x4(bf[2*nb][0], bf[2*nb][1], bf[2*nb+1][0], bf[2*nb+1][1],
                            Bs_a + b_lane_off + (uint32_t)(nb * 16 * GSTRW) * 4 + ks * 32);
#pragma unroll
            for (int mi = 0; mi < 4; mi++)
#pragma unroll
                for (int ni = 0; ni < 4; ni++)
                    mma_f16(c[mi][ni][0], c[mi][ni][1], c[mi][ni][2], c[mi][ni][3],
                            af[mi][0], af[mi][1], af[mi][2], af[mi][3],
                            bf[ni][0], bf[ni][1]);
        }
    }

    if (half_out) {
        __half* C = (__half*)Cv;
#pragma unroll
        for (int mi = 0; mi < 4; mi++)
#pragma unroll
            for (int ni = 0; ni < 4; ni++) {
                int row = bm + wm + mi * 16 + g;
                int col = bn + wn + ni * 8 + 2 * tg;
                *(uint32_t*)(C + (size_t)row * N + col)       = pack_h2(c[mi][ni][0], c[mi][ni][1]);
                *(uint32_t*)(C + (size_t)(row + 8) * N + col) = pack_h2(c[mi][ni][2], c[mi][ni][3]);
            }
    } else {
        float* C = (float*)Cv;
#pragma unroll
        for (int mi = 0; mi < 4; mi++)
#pragma unroll
            for (int ni = 0; ni < 4; ni++) {
                int row = bm + wm + mi * 16 + g;
                int col = bn + wn + ni * 8 + 2 * tg;
                *(float2*)(C + (size_t)row * N + col)       = make_float2(c[mi][ni][0], c[mi][ni][1]);
                *(float2*)(C + (size_t)(row + 8) * N + col) = make_float2(c[mi][ni][2], c[mi][ni][3]);
            }
    }
}

// ---------------------------------------------------------------------------
// fp16 tensor-core causal flash attention. ldmatrix K-frags; register P;
// diagonal-tile mma skipping (warp-uniform bounds).
// ---------------------------------------------------------------------------
#define FSTRW 36
#define FT_U32   (64 * FSTRW)
#define FA_SMEM_B (4 * FT_U32 * 4)             // 36864 B

__global__ __launch_bounds__(256, 2) void flash_attn_h(const __half* __restrict__ Qg,
                                                       const __half* __restrict__ Kg,
                                                       const __half* __restrict__ Vg,
                                                       __half* __restrict__ Og)
{
    extern __shared__ uint32_t sm[];
    const uint32_t sb = smem_u32addr(sm);

    const int qt   = (gridDim.x - 1) - blockIdx.x;   // heavy blocks first
    const int bh   = blockIdx.y;
    const int b    = bh >> 4;
    const int h    = bh & 15;
    const int tid  = threadIdx.x;
    const int lane = tid & 31;
    const int warp = tid >> 5;
    const int g    = lane >> 2;
    const int tg   = lane & 3;
    const int m0   = warp * 16;
    const int q0   = qt * 128;

    const size_t base = (size_t)b * S_ * D_ + (size_t)h * DH_;
    const int nkt = 2 * qt + 2;

    int crow[2], cc16[2];
#pragma unroll
    for (int it = 0; it < 2; it++) {
        int idx = it * 256 + tid;
        crow[it] = idx >> 3;
        cc16[it] = idx & 7;
    }

    auto load_tile = [&](int s, int k0) {
        uint32_t ksa = sb + (s * 2 * FT_U32) * 4;
        uint32_t vsa = ksa + FT_U32 * 4;
#pragma unroll
        for (int it = 0; it < 2; it++) {
            uint32_t off = (uint32_t)(crow[it] * FSTRW + cc16[it] * 4) * 4;
            cp_async16(ksa + off, Kg + base + (size_t)(k0 + crow[it]) * D_ + cc16[it] * 8);
            cp_async16(vsa + off, Vg + base + (size_t)(k0 + crow[it]) * D_ + cc16[it] * 8);
        }
        asm volatile("cp.async.commit_group;");
    };

    load_tile(0, 0);

    // K ldmatrix per-lane offset (token-row = n dim, d = k dim)
    const uint32_t kb_lane_off =
        (uint32_t)(((lane & 7) + 8 * (lane >> 4)) * FSTRW + 4 * ((lane >> 3) & 1)) * 4;

    // Q fragments straight from global
    uint32_t qf[4][4];
    {
        const __half* qr0 = Qg + base + (size_t)(q0 + m0 + g) * D_;
        const __half* qr1 = qr0 + 8 * D_;
#pragma unroll
        for (int ks = 0; ks < 4; ks++) {
            qf[ks][0] = *(const uint32_t*)(qr0 + ks * 16 + 2 * tg);
            qf[ks][1] = *(const uint32_t*)(qr1 + ks * 16 + 2 * tg);
            qf[ks][2] = *(const uint32_t*)(qr0 + ks * 16 + 2 * tg + 8);
            qf[ks][3] = *(const uint32_t*)(qr1 + ks * 16 + 2 * tg + 8);
        }
    }

    float o[8][4];
#pragma unroll
    for (int ni = 0; ni < 8; ni++)
#pragma unroll
        for (int f = 0; f < 4; f++) o[ni][f] = 0.f;
    float mrow[2] = {-1e30f, -1e30f};
    float lrow[2] = {0.f, 0.f};

    for (int kt = 0; kt < nkt; kt++) {
        const int buf = kt & 1;

        asm volatile("cp.async.wait_group 0;");
        __syncthreads();

        if (kt + 1 < nkt) load_tile(buf ^ 1, (kt + 1) * 64);

        const uint32_t ksa = sb + (buf * 2 * FT_U32) * 4;
        const uint32_t vsa = ksa + FT_U32 * 4;
        const int k0 = kt * 64;

        // warp-uniform visibility bounds for diagonal tiles
        int nb_cnt = 4, ks_cnt = 4;
        const bool diag = (kt >= 2 * qt);
        if (diag) {
            int lim = m0 + 15 - (k0 - q0);        // max visible col offset in tile
            int nic = (lim < 0) ? 0 : ((lim >> 3) + 1);
            if (nic > 8) nic = 8;
            nb_cnt = (nic + 1) >> 1;
            int ksc = (lim < 0) ? 0 : ((lim >> 4) + 1);
            if (ksc > 4) ksc = 4;
            ks_cnt = ksc;
        }

        // ---- S = Q K^T (only visible n-tile pairs) ----
        float s[8][4];
#pragma unroll
        for (int nb = 0; nb < 4; nb++) {
            if (nb < nb_cnt) {
                float* s0 = s[2*nb];
                float* s1 = s[2*nb+1];
                s0[0]=s0[1]=s0[2]=s0[3]=0.f;
                s1[0]=s1[1]=s1[2]=s1[3]=0.f;
#pragma unroll
                for (int ks = 0; ks < 4; ks++) {
                    uint32_t b0a, b1a, b0b, b1b;
                    ldmatrix_x4(b0a, b1a, b0b, b1b,
                                ksa + kb_lane_off + (uint32_t)(nb * 16 * FSTRW) * 4 + ks * 32);
                    mma_f16(s0[0], s0[1], s0[2], s0[3],
                            qf[ks][0], qf[ks][1], qf[ks][2], qf[ks][3], b0a, b1a);
                    mma_f16(s1[0], s1[1], s1[2], s1[3],
                            qf[ks][0], qf[ks][1], qf[ks][2], qf[ks][3], b0b, b1b);
                }
#pragma unroll
                for (int f = 0; f < 4; f++) { s0[f] *= 0.125f; s1[f] *= 0.125f; }
            } else {
                s[2*nb][0]=s[2*nb][1]=s[2*nb][2]=s[2*nb][3]=-1e30f;
                s[2*nb+1][0]=s[2*nb+1][1]=s[2*nb+1][2]=s[2*nb+1][3]=-1e30f;
            }
        }

        // ---- causal element mask on computed diagonal tiles ----
        if (diag) {
            int row0 = q0 + m0 + g;
            int row1 = row0 + 8;
#pragma unroll
            for (int ni = 0; ni < 8; ni++) {
                if (ni < 2 * nb_cnt) {
                    int c0 = k0 + ni * 8 + 2 * tg;
                    if (c0     > row0) s[ni][0] = -1e30f;
                    if (c0 + 1 > row0) s[ni][1] = -1e30f;
                    if (c0     > row1) s[ni][2] = -1e30f;
                    if (c0 + 1 > row1) s[ni][3] = -1e30f;
                }
            }
        }

        // ---- online softmax ----
#pragma unroll
        for (int r2 = 0; r2 < 2; r2++) {
            float mx = -1e30f;
#pragma unroll
            for (int ni = 0; ni < 8; ni++)
                mx = fmaxf(mx, fmaxf(s[ni][2 * r2], s[ni][2 * r2 + 1]));
            mx = fmaxf(mx, __shfl_xor_sync(0xffffffffu, mx, 1));
            mx = fmaxf(mx, __shfl_xor_sync(0xffffffffu, mx, 2));
            float mnew  = fmaxf(mrow[r2], mx);
            float alpha = __expf(mrow[r2] - mnew);
            mrow[r2] = mnew;
            float rs = 0.f;
#pragma unroll
            for (int ni = 0; ni < 8; ni++) {
                float p0 = __expf(s[ni][2 * r2]     - mnew);
                float p1 = __expf(s[ni][2 * r2 + 1] - mnew);
                s[ni][2 * r2] = p0; s[ni][2 * r2 + 1] = p1;
                rs += p0 + p1;
            }
            rs += __shfl_xor_sync(0xffffffffu, rs, 1);
            rs += __shfl_xor_sync(0xffffffffu, rs, 2);
            lrow[r2] = lrow[r2] * alpha + rs;
#pragma unroll
            for (int ni = 0; ni < 8; ni++) {
                o[ni][2 * r2]     *= alpha;
                o[ni][2 * r2 + 1] *= alpha;
            }
        }

        // ---- O += P V (skip fully-masked key groups) ----
#pragma unroll
        for (int ks = 0; ks < 4; ks++) {
            if (ks < ks_cnt) {
                uint32_t a0 = pack_h2(s[2*ks][0],   s[2*ks][1]);
                uint32_t a1 = pack_h2(s[2*ks][2],   s[2*ks][3]);
                uint32_t a2 = pack_h2(s[2*ks+1][0], s[2*ks+1][1]);
                uint32_t a3 = pack_h2(s[2*ks+1][2], s[2*ks+1][3]);
                uint32_t vrow = vsa + (uint32_t)(16 * ks + (lane & 15)) * (FSTRW * 4)
                                    + (uint32_t)(lane >> 4) * 16;
#pragma unroll
                for (int nb = 0; nb < 4; nb++) {
                    uint32_t r0, r1, r2, r3;
                    ldmatrix_x4_trans(r0, r1, r2, r3, vrow + (uint32_t)nb * 32);
                    mma_f16(o[2*nb][0],   o[2*nb][1],   o[2*nb][2],   o[2*nb][3],
                            a0, a1, a2, a3, r0, r1);
                    mma_f16(o[2*nb+1][0], o[2*nb+1][1], o[2*nb+1][2], o[2*nb+1][3],
                            a0, a1, a2, a3, r2, r3);
                }
            }
        }
    }

    // ---- epilogue (half output) ----
    const float inv0 = 1.f / lrow[0];
    const float inv1 = 1.f / lrow[1];
    const int row0 = q0 + m0 + g;
    __half* op0 = Og + base + (size_t)row0 * D_;
    __half* op1 = op0 + 8 * D_;
#pragma unroll
    for (int ni = 0; ni < 8; ni++) {
        int col = ni * 8 + 2 * tg;
        *(uint32_t*)(op0 + col) = pack_h2(o[ni][0] * inv0, o[ni][1] * inv0);
        *(uint32_t*)(op1 + col) = pack_h2(o[ni][2] * inv1, o[ni][3] * inv1);
    }
}

// ---------------------------------------------------------------------------
extern "C" void kernel_launch(void* const* d_in, const int* in_sizes, int n_in,
                              void* d_out, int out_size)
{
    const float* x  = (const float*)d_in[0];
    const float* Wq = (const float*)d_in[1];
    const float* Wk = (const float*)d_in[2];
    const float* Wv = (const float*)d_in[3];
    const float* Wo = (const float*)d_in[4];
    float* out = (float*)d_out;

    __half *q, *k, *v, *o, *xh, *wh;
    cudaGetSymbolAddress((void**)&q,  g_q);
    cudaGetSymbolAddress((void**)&k,  g_k);
    cudaGetSymbolAddress((void**)&v,  g_v);
    cudaGetSymbolAddress((void**)&o,  g_o);
    cudaGetSymbolAddress((void**)&xh, g_xh);
    cudaGetSymbolAddress((void**)&wh, g_wh);
    const size_t WSZ = (size_t)D_ * D_;

    static bool attr_set = false;
    if (!attr_set) {
        cudaFuncSetAttribute(flash_attn_h,
                             cudaFuncAttributeMaxDynamicSharedMemorySize, FA_SMEM_B);
        cudaFuncSetAttribute(gemm_h,
                             cudaFuncAttributeMaxDynamicSharedMemorySize, G_SMEM_B);
        attr_set = true;
    }

    cvt_h_kernel<<<dim3(1024, 1, 8), 256>>>(x, Wq, Wk, Wv, Wo);

    gemm_h<<<dim3(D_ / 128, MTOT / 128, 3), 256, G_SMEM_B>>>(
        xh, wh + 0 * WSZ, wh + 1 * WSZ, wh + 2 * WSZ, q, k, v, 1);

    flash_attn_h<<<dim3(S_ / 128, B_ * H_), 256, FA_SMEM_B>>>(q, k, v, o);

    gemm_h<<<dim3(D_ / 128, MTOT / 128, 1), 256, G_SMEM_B>>>(
        o, wh + 3 * WSZ, wh + 3 * WSZ, wh + 3 * WSZ, out, out, out, 0);
}